// round 1
// baseline (speedup 1.0000x reference)
#include <cuda_runtime.h>
#include <math.h>

// ---- problem dims ----
#define Bv 4
#define Sv 2048
#define Hv 1024
#define NHv 16
#define HDv 64
#define FFv 4096
#define Mv (Bv*Sv)   // 8192 rows

// ---- scratch (device globals; no allocation allowed) ----
__device__ float g_q[Mv*Hv];
__device__ float g_k[Mv*Hv];
__device__ float g_v[Mv*Hv];
__device__ float g_ctx[Mv*Hv];
__device__ float g_res1[Mv*Hv];
__device__ float g_x1[Mv*Hv];
__device__ float g_ff[(size_t)Mv*FFv];
__device__ float g_res2[Mv*Hv];

// ============================================================
// Generic SGEMM: C[M,N] = A[M,K] @ B[K,N] + bias[N]
//   act=1: gelu(tanh approx) applied to (acc+bias)
//   resid != null: add resid[row,col] after activation
// BM=128, BN=128, BK=16, 256 threads, 8x8 per thread.
// All dims assumed divisible by tile sizes (true here).
// ============================================================
__global__ __launch_bounds__(256) void sgemm_kernel(
    const float* __restrict__ A, const float* __restrict__ B,
    const float* __restrict__ bias, const float* __restrict__ resid,
    float* __restrict__ C, int N, int K, int act)
{
    const int BM = 128, BN = 128, BK = 16;
    __shared__ float As[BK][BM];
    __shared__ float Bs[BK][BN];

    int t  = threadIdx.x;
    int bm = blockIdx.y * BM;
    int bn = blockIdx.x * BN;
    int tx = t % 16, ty = t / 16;

    float acc[8][8];
    #pragma unroll
    for (int i = 0; i < 8; i++)
        #pragma unroll
        for (int j = 0; j < 8; j++) acc[i][j] = 0.f;

    int aRow = t / 4;          // 0..63
    int aCol = (t % 4) * 4;    // 0,4,8,12
    int bRow = t / 32;         // 0..7
    int bCol = (t % 32) * 4;   // 0..124

    for (int k0 = 0; k0 < K; k0 += BK) {
        #pragma unroll
        for (int r = 0; r < 2; r++) {
            int row = aRow + r * 64;
            float4 av = *(const float4*)&A[(size_t)(bm + row) * K + k0 + aCol];
            As[aCol + 0][row] = av.x;
            As[aCol + 1][row] = av.y;
            As[aCol + 2][row] = av.z;
            As[aCol + 3][row] = av.w;
        }
        #pragma unroll
        for (int r = 0; r < 2; r++) {
            int row = bRow + r * 8;
            float4 bv = *(const float4*)&B[(size_t)(k0 + row) * N + bn + bCol];
            *(float4*)&Bs[row][bCol] = bv;
        }
        __syncthreads();

        #pragma unroll
        for (int kk = 0; kk < BK; kk++) {
            float ra[8], rb[8];
            #pragma unroll
            for (int i = 0; i < 8; i++) ra[i] = As[kk][ty * 8 + i];
            #pragma unroll
            for (int j = 0; j < 8; j++) rb[j] = Bs[kk][tx * 8 + j];
            #pragma unroll
            for (int i = 0; i < 8; i++)
                #pragma unroll
                for (int j = 0; j < 8; j++)
                    acc[i][j] += ra[i] * rb[j];
        }
        __syncthreads();
    }

    #pragma unroll
    for (int i = 0; i < 8; i++) {
        int row = bm + ty * 8 + i;
        #pragma unroll
        for (int j = 0; j < 8; j++) {
            int col = bn + tx * 8 + j;
            float v = acc[i][j] + bias[col];
            if (act) {
                float xg = v;
                v = 0.5f * xg * (1.0f + tanhf(0.7978845608028654f *
                        (xg + 0.044715f * xg * xg * xg)));
            }
            if (resid) v += resid[(size_t)row * N + col];
            C[(size_t)row * N + col] = v;
        }
    }
}

// ============================================================
// Flash attention (fp32): one CTA handles 64 query rows of one (b,h).
// QKV stored [B,S,H]; head slice has stride H.
// 256 threads = 16x16 grid, each thread owns 4x4 of the 64x64 tiles.
// Online softmax with shfl reductions inside 16-lane groups
// (lanes 0-15 / 16-31 each map to one row-group ty).
// ============================================================
__global__ __launch_bounds__(256) void attn_kernel(
    const float* __restrict__ Q, const float* __restrict__ K,
    const float* __restrict__ V, const float* __restrict__ mask,
    float* __restrict__ O)
{
    extern __shared__ float smBuf[];
    float* Qs = smBuf;            // [64][65]
    float* Ks = Qs + 64 * 65;     // [64][65]
    float* Vs = Ks + 64 * 65;     // [64][65]
    float* Ps = Vs + 64 * 65;     // [64][65]

    int qb = blockIdx.x * 64;
    int h  = blockIdx.y;
    int b  = blockIdx.z;
    int t  = threadIdx.x;
    int tx = t % 16, ty = t / 16;

    const size_t base = ((size_t)b * Sv) * Hv + (size_t)h * HDv;

    // load Q tile (64x64)
    for (int idx = t; idx < 64 * 16; idx += 256) {
        int r  = idx / 16;
        int c4 = (idx % 16) * 4;
        float4 qv = *(const float4*)&Q[base + (size_t)(qb + r) * Hv + c4];
        Qs[r * 65 + c4 + 0] = qv.x;
        Qs[r * 65 + c4 + 1] = qv.y;
        Qs[r * 65 + c4 + 2] = qv.z;
        Qs[r * 65 + c4 + 3] = qv.w;
    }

    float m[4], l[4], o[4][4];
    #pragma unroll
    for (int i = 0; i < 4; i++) {
        m[i] = -INFINITY; l[i] = 0.f;
        #pragma unroll
        for (int j = 0; j < 4; j++) o[i][j] = 0.f;
    }

    const float* maskRow = mask + (size_t)b * Sv;

    for (int kb = 0; kb < Sv; kb += 64) {
        __syncthreads();  // previous iteration done with Ks/Vs
        for (int idx = t; idx < 64 * 16; idx += 256) {
            int r  = idx / 16;
            int c4 = (idx % 16) * 4;
            float4 kv = *(const float4*)&K[base + (size_t)(kb + r) * Hv + c4];
            Ks[r * 65 + c4 + 0] = kv.x;
            Ks[r * 65 + c4 + 1] = kv.y;
            Ks[r * 65 + c4 + 2] = kv.z;
            Ks[r * 65 + c4 + 3] = kv.w;
            float4 vv = *(const float4*)&V[base + (size_t)(kb + r) * Hv + c4];
            Vs[r * 65 + c4 + 0] = vv.x;
            Vs[r * 65 + c4 + 1] = vv.y;
            Vs[r * 65 + c4 + 2] = vv.z;
            Vs[r * 65 + c4 + 3] = vv.w;
        }
        __syncthreads();

        // S = Q K^T (4x4 per thread)
        float s[4][4];
        #pragma unroll
        for (int i = 0; i < 4; i++)
            #pragma unroll
            for (int j = 0; j < 4; j++) s[i][j] = 0.f;

        #pragma unroll 8
        for (int d = 0; d < 64; d++) {
            float qr[4], kc[4];
            #pragma unroll
            for (int i = 0; i < 4; i++) qr[i] = Qs[(ty * 4 + i) * 65 + d];
            #pragma unroll
            for (int j = 0; j < 4; j++) kc[j] = Ks[(tx * 4 + j) * 65 + d];
            #pragma unroll
            for (int i = 0; i < 4; i++)
                #pragma unroll
                for (int j = 0; j < 4; j++)
                    s[i][j] += qr[i] * kc[j];
        }

        float mk[4];
        #pragma unroll
        for (int j = 0; j < 4; j++) mk[j] = maskRow[kb + tx * 4 + j];
        #pragma unroll
        for (int i = 0; i < 4; i++)
            #pragma unroll
            for (int j = 0; j < 4; j++)
                s[i][j] = s[i][j] * 0.125f + mk[j];

        // online softmax per row
        #pragma unroll
        for (int i = 0; i < 4; i++) {
            float tmax = fmaxf(fmaxf(s[i][0], s[i][1]), fmaxf(s[i][2], s[i][3]));
            #pragma unroll
            for (int off = 8; off >= 1; off >>= 1)
                tmax = fmaxf(tmax, __shfl_xor_sync(0xffffffffu, tmax, off));
            float mn   = fmaxf(m[i], tmax);
            float corr = __expf(m[i] - mn);
            float ls   = 0.f;
            #pragma unroll
            for (int j = 0; j < 4; j++) { s[i][j] = __expf(s[i][j] - mn); ls += s[i][j]; }
            #pragma unroll
            for (int off = 8; off >= 1; off >>= 1)
                ls += __shfl_xor_sync(0xffffffffu, ls, off);
            l[i] = l[i] * corr + ls;
            m[i] = mn;
            #pragma unroll
            for (int j = 0; j < 4; j++) o[i][j] *= corr;
            #pragma unroll
            for (int j = 0; j < 4; j++)
                Ps[(ty * 4 + i) * 65 + tx * 4 + j] = s[i][j];
        }
        __syncthreads();

        // O += P @ V
        #pragma unroll 4
        for (int c = 0; c < 64; c++) {
            float pv[4];
            #pragma unroll
            for (int i = 0; i < 4; i++) pv[i] = Ps[(ty * 4 + i) * 65 + c];
            float v0 = Vs[c * 65 + tx * 4 + 0];
            float v1 = Vs[c * 65 + tx * 4 + 1];
            float v2 = Vs[c * 65 + tx * 4 + 2];
            float v3 = Vs[c * 65 + tx * 4 + 3];
            #pragma unroll
            for (int i = 0; i < 4; i++) {
                o[i][0] += pv[i] * v0;
                o[i][1] += pv[i] * v1;
                o[i][2] += pv[i] * v2;
                o[i][3] += pv[i] * v3;
            }
        }
    }

    #pragma unroll
    for (int i = 0; i < 4; i++) {
        float inv = 1.0f / l[i];
        #pragma unroll
        for (int j = 0; j < 4; j++)
            O[base + (size_t)(qb + ty * 4 + i) * Hv + tx * 4 + j] = o[i][j] * inv;
    }
}

// ============================================================
// LayerNorm over last dim (1024). One CTA (256 thr) per row.
// ============================================================
__global__ __launch_bounds__(256) void ln_kernel(
    const float* __restrict__ X, const float* __restrict__ gam,
    const float* __restrict__ bet, float* __restrict__ Y)
{
    __shared__ float red[256];
    int row = blockIdx.x;
    int t   = threadIdx.x;
    const float* xr = X + (size_t)row * Hv;

    float4 x4 = *(const float4*)&xr[t * 4];
    float ssum = x4.x + x4.y + x4.z + x4.w;
    red[t] = ssum; __syncthreads();
    #pragma unroll
    for (int s = 128; s > 0; s >>= 1) {
        if (t < s) red[t] += red[t + s];
        __syncthreads();
    }
    float mean = red[0] * (1.0f / Hv);
    __syncthreads();

    float dx = x4.x - mean, dy = x4.y - mean, dz = x4.z - mean, dw = x4.w - mean;
    red[t] = dx * dx + dy * dy + dz * dz + dw * dw; __syncthreads();
    #pragma unroll
    for (int s = 128; s > 0; s >>= 1) {
        if (t < s) red[t] += red[t + s];
        __syncthreads();
    }
    float rstd = rsqrtf(red[0] * (1.0f / Hv) + 1e-12f);

    float4 gg = *(const float4*)&gam[t * 4];
    float4 bb = *(const float4*)&bet[t * 4];
    float4 out;
    out.x = dx * rstd * gg.x + bb.x;
    out.y = dy * rstd * gg.y + bb.y;
    out.z = dz * rstd * gg.z + bb.z;
    out.w = dw * rstd * gg.w + bb.w;
    *(float4*)&Y[(size_t)row * Hv + t * 4] = out;
}

// ============================================================
// Launch
// ============================================================
extern "C" void kernel_launch(void* const* d_in, const int* in_sizes, int n_in,
                              void* d_out, int out_size)
{
    const float* x    = (const float*)d_in[0];
    const float* mask = (const float*)d_in[1];
    const float* Wq   = (const float*)d_in[2];
    const float* bq   = (const float*)d_in[3];
    const float* Wk   = (const float*)d_in[4];
    const float* bk   = (const float*)d_in[5];
    const float* Wv   = (const float*)d_in[6];
    const float* bv   = (const float*)d_in[7];
    const float* Wo   = (const float*)d_in[8];
    const float* bo   = (const float*)d_in[9];
    const float* ln1g = (const float*)d_in[10];
    const float* ln1b = (const float*)d_in[11];
    const float* W1   = (const float*)d_in[12];
    const float* b1   = (const float*)d_in[13];
    const float* W2   = (const float*)d_in[14];
    const float* b2   = (const float*)d_in[15];
    const float* ln2g = (const float*)d_in[16];
    const float* ln2b = (const float*)d_in[17];
    float* out = (float*)d_out;

    float *q, *k, *v, *ctx, *res1, *x1, *ff, *res2;
    cudaGetSymbolAddress((void**)&q,    g_q);
    cudaGetSymbolAddress((void**)&k,    g_k);
    cudaGetSymbolAddress((void**)&v,    g_v);
    cudaGetSymbolAddress((void**)&ctx,  g_ctx);
    cudaGetSymbolAddress((void**)&res1, g_res1);
    cudaGetSymbolAddress((void**)&x1,   g_x1);
    cudaGetSymbolAddress((void**)&ff,   g_ff);
    cudaGetSymbolAddress((void**)&res2, g_res2);

    const int attnSmem = 4 * 64 * 65 * sizeof(float);  // 66560 B
    cudaFuncSetAttribute(attn_kernel,
                         cudaFuncAttributeMaxDynamicSharedMemorySize, attnSmem);

    dim3 gH(Hv / 128, Mv / 128);    // N=1024 GEMMs: (8, 64)
    dim3 gF(FFv / 128, Mv / 128);   // N=4096 GEMM:  (32, 64)

    // QKV projections
    sgemm_kernel<<<gH, 256>>>(x, Wq, bq, nullptr, q, Hv, Hv, 0);
    sgemm_kernel<<<gH, 256>>>(x, Wk, bk, nullptr, k, Hv, Hv, 0);
    sgemm_kernel<<<gH, 256>>>(x, Wv, bv, nullptr, v, Hv, Hv, 0);

    // attention
    dim3 gA(Sv / 64, NHv, Bv);
    attn_kernel<<<gA, 256, attnSmem>>>(q, k, v, mask, ctx);

    // output projection + residual, then LN1
    sgemm_kernel<<<gH, 256>>>(ctx, Wo, bo, x, res1, Hv, Hv, 0);
    ln_kernel<<<Mv, 256>>>(res1, ln1g, ln1b, x1);

    // FFN
    sgemm_kernel<<<gF, 256>>>(x1, W1, b1, nullptr, ff, FFv, Hv, 1);
    sgemm_kernel<<<gH, 256>>>(ff, W2, b2, x1, res2, Hv, FFv, 0);
    ln_kernel<<<Mv, 256>>>(res2, ln2g, ln2b, out);
}

// round 3
// speedup vs baseline: 1.7722x; 1.7722x over previous
#include <cuda_runtime.h>
#include <cuda_bf16.h>
#include <math.h>
#include <stdint.h>

// ---- problem dims ----
#define Bv 4
#define Sv 2048
#define Hv 1024
#define NHv 16
#define HDv 64
#define FFv 4096
#define Mv (Bv*Sv)   // 8192 rows

// ---- scratch (device globals; no allocation allowed) ----
__device__ float g_q[Mv*Hv];
__device__ float g_k[Mv*Hv];
__device__ float g_v[Mv*Hv];
__device__ float g_res1[Mv*Hv];
__device__ float g_x1[Mv*Hv];
__device__ float g_res2[Mv*Hv];

// split activations (reused: x -> ctx -> x1)
__device__ __nv_bfloat16 g_ah[Mv*Hv];
__device__ __nv_bfloat16 g_al[Mv*Hv];
// split FF intermediate
__device__ __nv_bfloat16 g_fh[Mv*FFv];
__device__ __nv_bfloat16 g_fl[Mv*FFv];
// transposed+split weights  (Wt is [N,K] K-major)
__device__ __nv_bfloat16 g_wqh[Hv*Hv], g_wql[Hv*Hv];
__device__ __nv_bfloat16 g_wkh[Hv*Hv], g_wkl[Hv*Hv];
__device__ __nv_bfloat16 g_wvh[Hv*Hv], g_wvl[Hv*Hv];
__device__ __nv_bfloat16 g_woh[Hv*Hv], g_wol[Hv*Hv];
__device__ __nv_bfloat16 g_w1h[FFv*Hv], g_w1l[FFv*Hv];   // [4096,1024]
__device__ __nv_bfloat16 g_w2h[Hv*FFv], g_w2l[Hv*FFv];   // [1024,4096]

// ============================================================
// helpers
// ============================================================
__device__ __forceinline__ uint32_t s2u(const void* p) {
    uint32_t a;
    asm("{ .reg .u64 t; cvta.to.shared.u64 t, %1; cvt.u32.u64 %0, t; }" : "=r"(a) : "l"(p));
    return a;
}
__device__ __forceinline__ void split2(float a, __nv_bfloat16& h, __nv_bfloat16& l) {
    h = __float2bfloat16(a);
    l = __float2bfloat16(a - __bfloat162float(h));
}
__device__ __forceinline__ void cpasync16(uint32_t dst, const void* src) {
    asm volatile("cp.async.cg.shared.global [%0], [%1], 16;" :: "r"(dst), "l"(src));
}
#define CP_COMMIT() asm volatile("cp.async.commit_group;" ::: "memory")
#define CP_WAIT(n)  asm volatile("cp.async.wait_group %0;" :: "n"(n) : "memory")

__device__ __forceinline__ void ldsm4(uint32_t& r0, uint32_t& r1, uint32_t& r2, uint32_t& r3,
                                      uint32_t addr) {
    asm volatile("ldmatrix.sync.aligned.m8n8.x4.shared.b16 {%0,%1,%2,%3}, [%4];"
                 : "=r"(r0), "=r"(r1), "=r"(r2), "=r"(r3) : "r"(addr));
}
__device__ __forceinline__ void mma16816(float* d, const uint32_t* a, const uint32_t* b) {
    asm volatile("mma.sync.aligned.m16n8k16.row.col.f32.bf16.bf16.f32 "
                 "{%0,%1,%2,%3}, {%4,%5,%6,%7}, {%8,%9}, {%0,%1,%2,%3};"
                 : "+f"(d[0]), "+f"(d[1]), "+f"(d[2]), "+f"(d[3])
                 : "r"(a[0]), "r"(a[1]), "r"(a[2]), "r"(a[3]), "r"(b[0]), "r"(b[1]));
}

// ============================================================
// Split-bf16 tensor-core GEMM via mma.sync:
//   C[M,N] = A[M,K] @ Bt[N,K]^T  with A=(Ah+Al), B=(Bh+Bl), 3 MMA passes.
// BM=128, BN=128, BK=32; 256 threads (8 warps, 2x4 grid, 64x32 warp tile);
// cp.async 2-stage double buffer; swizzled smem; fused epilogue.
// ============================================================
#define BKc 32
#define TILE_BYTES 8192          // 128 rows * 64 B
#define STAGE_BYTES 32768        // Ah, Al, Bh, Bl
#define GSMEM 65536

__global__ __launch_bounds__(256) void gemm_mma(
    const __nv_bfloat16* __restrict__ Ah, const __nv_bfloat16* __restrict__ Al,
    const __nv_bfloat16* __restrict__ Bh, const __nv_bfloat16* __restrict__ Bl,
    const float* __restrict__ bias, const float* __restrict__ resid,
    float* __restrict__ C, __nv_bfloat16* __restrict__ Ch, __nv_bfloat16* __restrict__ Cl,
    int K, int N, int act)
{
    extern __shared__ __align__(1024) char smem[];
    uint32_t sb = s2u(smem);
    int t = threadIdx.x, lane = t & 31, warp = t >> 5;
    int wm = warp & 1, wn = warp >> 1;       // 2 x 4 warp grid
    int bm = blockIdx.y * 128, bn = blockIdx.x * 128;

    const __nv_bfloat16* srcs[4];
    srcs[0] = Ah + (size_t)bm * K;
    srcs[1] = Al + (size_t)bm * K;
    srcs[2] = Bh + (size_t)bn * K;
    srcs[3] = Bl + (size_t)bn * K;

    float acc[4][4][4];
    #pragma unroll
    for (int i = 0; i < 4; i++)
        #pragma unroll
        for (int j = 0; j < 4; j++)
            #pragma unroll
            for (int e = 0; e < 4; e++) acc[i][j][e] = 0.f;

    int nc = K / BKc;

    // ---- stage loader: 2048 x 16B chunks, 8 per thread ----
    auto load_stage = [&](int s, int c) {
        int kb = c * BKc;
        #pragma unroll
        for (int i = 0; i < 8; i++) {
            int idx = i * 256 + t;
            int o   = idx >> 9;
            int rem = idx & 511;
            int r   = rem >> 2;
            int ch  = rem & 3;
            const __nv_bfloat16* src = srcs[o] + (size_t)r * K + kb + ch * 8;
            uint32_t dst = sb + s * STAGE_BYTES + o * TILE_BYTES
                         + r * 64 + ((ch ^ ((r >> 1) & 3)) << 4);
            cpasync16(dst, src);
        }
    };

    load_stage(0, 0);
    CP_COMMIT();

    for (int c = 0; c < nc; c++) {
        int s = c & 1;
        if (c + 1 < nc) {
            load_stage(s ^ 1, c + 1);
            CP_COMMIT();
            CP_WAIT(1);
        } else {
            CP_WAIT(0);
        }
        __syncthreads();

        uint32_t tb = sb + s * STAGE_BYTES;
        int g = lane >> 3;

        #pragma unroll
        for (int ks = 0; ks < 2; ks++) {
            uint32_t aH[4][4], aL[4][4], bH[4][2], bL[4][2];
            // A fragments: lanes 0-7 rows m0-7 @k0, 8-15 rows m8-15 @k0,
            //              16-23 rows m0-7 @k8, 24-31 rows m8-15 @k8
            {
                int arow_off = ((g & 1) << 3) + (lane & 7);
                int ach = 2 * ks + (g >> 1);
                #pragma unroll
                for (int mf = 0; mf < 4; mf++) {
                    int row = wm * 64 + mf * 16 + arow_off;
                    uint32_t ad = tb + row * 64 + ((ach ^ ((row >> 1) & 3)) << 4);
                    ldsm4(aH[mf][0], aH[mf][1], aH[mf][2], aH[mf][3], ad);
                    ldsm4(aL[mf][0], aL[mf][1], aL[mf][2], aL[mf][3], ad + TILE_BYTES);
                }
            }
            // B fragments: lanes 0-7 n0-7 @k0, 8-15 n0-7 @k8,
            //              16-23 n8-15 @k0, 24-31 n8-15 @k8
            {
                int brow_off = ((g >> 1) << 3) + (lane & 7);
                int bch = 2 * ks + (g & 1);
                #pragma unroll
                for (int np = 0; np < 2; np++) {
                    int row = wn * 32 + np * 16 + brow_off;
                    uint32_t bd = tb + 2 * TILE_BYTES + row * 64
                                + ((bch ^ ((row >> 1) & 3)) << 4);
                    ldsm4(bH[2*np][0], bH[2*np][1], bH[2*np+1][0], bH[2*np+1][1], bd);
                    ldsm4(bL[2*np][0], bL[2*np][1], bL[2*np+1][0], bL[2*np+1][1],
                          bd + TILE_BYTES);
                }
            }
            #pragma unroll
            for (int mf = 0; mf < 4; mf++)
                #pragma unroll
                for (int nf = 0; nf < 4; nf++) {
                    mma16816(acc[mf][nf], aH[mf], bH[nf]);
                    mma16816(acc[mf][nf], aH[mf], bL[nf]);
                    mma16816(acc[mf][nf], aL[mf], bH[nf]);
                }
        }
        __syncthreads();
    }

    // ---- epilogue ----
    #pragma unroll
    for (int mf = 0; mf < 4; mf++) {
        int r0 = bm + wm * 64 + mf * 16 + (lane >> 2);
        #pragma unroll
        for (int nf = 0; nf < 4; nf++) {
            int j = bn + wn * 32 + nf * 8 + (lane & 3) * 2;
            float b0 = bias[j], b1 = bias[j + 1];
            #pragma unroll
            for (int half = 0; half < 2; half++) {
                int row = r0 + half * 8;
                float v0 = acc[mf][nf][half * 2 + 0] + b0;
                float v1 = acc[mf][nf][half * 2 + 1] + b1;
                if (act) {
                    float xg = v0;
                    v0 = 0.5f * xg * (1.0f + tanhf(0.7978845608028654f *
                            (xg + 0.044715f * xg * xg * xg)));
                    xg = v1;
                    v1 = 0.5f * xg * (1.0f + tanhf(0.7978845608028654f *
                            (xg + 0.044715f * xg * xg * xg)));
                }
                size_t o = (size_t)row * N + j;
                if (resid) { v0 += resid[o]; v1 += resid[o + 1]; }
                if (C) { C[o] = v0; C[o + 1] = v1; }
                if (Ch) {
                    __nv_bfloat16 h, l;
                    split2(v0, h, l); Ch[o]     = h; Cl[o]     = l;
                    split2(v1, h, l); Ch[o + 1] = h; Cl[o + 1] = l;
                }
            }
        }
    }
}

// ============================================================
// split: fp32 -> (hi, lo) bf16
// ============================================================
__global__ __launch_bounds__(256) void split_k(
    const float* __restrict__ X, __nv_bfloat16* __restrict__ H,
    __nv_bfloat16* __restrict__ L, int n)
{
    int i = (blockIdx.x * 256 + threadIdx.x) * 4;
    if (i >= n) return;
    float4 x4 = *(const float4*)&X[i];
    __nv_bfloat16 h0, l0, h1, l1, h2, l2, h3, l3;
    split2(x4.x, h0, l0); split2(x4.y, h1, l1);
    split2(x4.z, h2, l2); split2(x4.w, h3, l3);
    H[i] = h0; H[i + 1] = h1; H[i + 2] = h2; H[i + 3] = h3;
    L[i] = l0; L[i + 1] = l1; L[i + 2] = l2; L[i + 3] = l3;
}

// ============================================================
// transpose + split: W[K,N] fp32 -> T[N,K] bf16 hi/lo
// ============================================================
__global__ void transpose_split(const float* __restrict__ W,
                                __nv_bfloat16* __restrict__ Th,
                                __nv_bfloat16* __restrict__ Tl, int K, int N)
{
    __shared__ float tile[32][33];
    int bx = blockIdx.x * 32;  // N dim
    int by = blockIdx.y * 32;  // K dim
    int tx = threadIdx.x, ty = threadIdx.y;
    #pragma unroll
    for (int j = 0; j < 32; j += 8)
        tile[ty + j][tx] = W[(size_t)(by + ty + j) * N + bx + tx];
    __syncthreads();
    #pragma unroll
    for (int j = 0; j < 32; j += 8) {
        float v = tile[tx][ty + j];
        __nv_bfloat16 h, l;
        split2(v, h, l);
        size_t o = (size_t)(bx + ty + j) * K + by + tx;
        Th[o] = h; Tl[o] = l;
    }
}

// ============================================================
// Flash attention (fp32), writes ctx as bf16 hi/lo splits.
// ============================================================
__global__ __launch_bounds__(256) void attn_kernel(
    const float* __restrict__ Q, const float* __restrict__ K,
    const float* __restrict__ V, const float* __restrict__ mask,
    __nv_bfloat16* __restrict__ Oh, __nv_bfloat16* __restrict__ Ol)
{
    extern __shared__ float smBuf[];
    float* Qs = smBuf;
    float* Ks = Qs + 64 * 65;
    float* Vs = Ks + 64 * 65;
    float* Ps = Vs + 64 * 65;

    int qb = blockIdx.x * 64;
    int h  = blockIdx.y;
    int b  = blockIdx.z;
    int t  = threadIdx.x;
    int tx = t % 16, ty = t / 16;

    const size_t base = ((size_t)b * Sv) * Hv + (size_t)h * HDv;

    for (int idx = t; idx < 64 * 16; idx += 256) {
        int r  = idx / 16;
        int c4 = (idx % 16) * 4;
        float4 qv = *(const float4*)&Q[base + (size_t)(qb + r) * Hv + c4];
        Qs[r * 65 + c4 + 0] = qv.x; Qs[r * 65 + c4 + 1] = qv.y;
        Qs[r * 65 + c4 + 2] = qv.z; Qs[r * 65 + c4 + 3] = qv.w;
    }

    float m[4], l[4], o[4][4];
    #pragma unroll
    for (int i = 0; i < 4; i++) {
        m[i] = -INFINITY; l[i] = 0.f;
        #pragma unroll
        for (int j = 0; j < 4; j++) o[i][j] = 0.f;
    }
    const float* maskRow = mask + (size_t)b * Sv;

    for (int kb = 0; kb < Sv; kb += 64) {
        __syncthreads();
        for (int idx = t; idx < 64 * 16; idx += 256) {
            int r  = idx / 16;
            int c4 = (idx % 16) * 4;
            float4 kv = *(const float4*)&K[base + (size_t)(kb + r) * Hv + c4];
            Ks[r * 65 + c4 + 0] = kv.x; Ks[r * 65 + c4 + 1] = kv.y;
            Ks[r * 65 + c4 + 2] = kv.z; Ks[r * 65 + c4 + 3] = kv.w;
            float4 vv = *(const float4*)&V[base + (size_t)(kb + r) * Hv + c4];
            Vs[r * 65 + c4 + 0] = vv.x; Vs[r * 65 + c4 + 1] = vv.y;
            Vs[r * 65 + c4 + 2] = vv.z; Vs[r * 65 + c4 + 3] = vv.w;
        }
        __syncthreads();

        float s[4][4];
        #pragma unroll
        for (int i = 0; i < 4; i++)
            #pragma unroll
            for (int j = 0; j < 4; j++) s[i][j] = 0.f;

        #pragma unroll 8
        for (int d = 0; d < 64; d++) {
            float qr[4], kc[4];
            #pragma unroll
            for (int i = 0; i < 4; i++) qr[i] = Qs[(ty * 4 + i) * 65 + d];
            #pragma unroll
            for (int j = 0; j < 4; j++) kc[j] = Ks[(tx * 4 + j) * 65 + d];
            #pragma unroll
            for (int i = 0; i < 4; i++)
                #pragma unroll
                for (int j = 0; j < 4; j++)
                    s[i][j] += qr[i] * kc[j];
        }

        float mk[4];
        #pragma unroll
        for (int j = 0; j < 4; j++) mk[j] = maskRow[kb + tx * 4 + j];
        #pragma unroll
        for (int i = 0; i < 4; i++)
            #pragma unroll
            for (int j = 0; j < 4; j++)
                s[i][j] = s[i][j] * 0.125f + mk[j];

        #pragma unroll
        for (int i = 0; i < 4; i++) {
            float tmax = fmaxf(fmaxf(s[i][0], s[i][1]), fmaxf(s[i][2], s[i][3]));
            #pragma unroll
            for (int off = 8; off >= 1; off >>= 1)
                tmax = fmaxf(tmax, __shfl_xor_sync(0xffffffffu, tmax, off));
            float mn   = fmaxf(m[i], tmax);
            float corr = __expf(m[i] - mn);
            float ls   = 0.f;
            #pragma unroll
            for (int j = 0; j < 4; j++) { s[i][j] = __expf(s[i][j] - mn); ls += s[i][j]; }
            #pragma unroll
            for (int off = 8; off >= 1; off >>= 1)
                ls += __shfl_xor_sync(0xffffffffu, ls, off);
            l[i] = l[i] * corr + ls;
            m[i] = mn;
            #pragma unroll
            for (int j = 0; j < 4; j++) o[i][j] *= corr;
            #pragma unroll
            for (int j = 0; j < 4; j++)
                Ps[(ty * 4 + i) * 65 + tx * 4 + j] = s[i][j];
        }
        __syncthreads();

        #pragma unroll 4
        for (int c = 0; c < 64; c++) {
            float pv[4];
            #pragma unroll
            for (int i = 0; i < 4; i++) pv[i] = Ps[(ty * 4 + i) * 65 + c];
            float v0 = Vs[c * 65 + tx * 4 + 0];
            float v1 = Vs[c * 65 + tx * 4 + 1];
            float v2 = Vs[c * 65 + tx * 4 + 2];
            float v3 = Vs[c * 65 + tx * 4 + 3];
            #pragma unroll
            for (int i = 0; i < 4; i++) {
                o[i][0] += pv[i] * v0; o[i][1] += pv[i] * v1;
                o[i][2] += pv[i] * v2; o[i][3] += pv[i] * v3;
            }
        }
    }

    #pragma unroll
    for (int i = 0; i < 4; i++) {
        float inv = 1.0f / l[i];
        #pragma unroll
        for (int j = 0; j < 4; j++) {
            float v = o[i][j] * inv;
            __nv_bfloat16 hh, ll;
            split2(v, hh, ll);
            size_t off = base + (size_t)(qb + ty * 4 + i) * Hv + tx * 4 + j;
            Oh[off] = hh; Ol[off] = ll;
        }
    }
}

// ============================================================
// LayerNorm; optionally also emits bf16 hi/lo splits.
// ============================================================
__global__ __launch_bounds__(256) void ln_kernel(
    const float* __restrict__ X, const float* __restrict__ gam,
    const float* __restrict__ bet, float* __restrict__ Y,
    __nv_bfloat16* __restrict__ Oh, __nv_bfloat16* __restrict__ Ol)
{
    __shared__ float red[256];
    int row = blockIdx.x;
    int t   = threadIdx.x;
    const float* xr = X + (size_t)row * Hv;

    float4 x4 = *(const float4*)&xr[t * 4];
    red[t] = x4.x + x4.y + x4.z + x4.w; __syncthreads();
    #pragma unroll
    for (int s = 128; s > 0; s >>= 1) {
        if (t < s) red[t] += red[t + s];
        __syncthreads();
    }
    float mean = red[0] * (1.0f / Hv);
    __syncthreads();

    float dx = x4.x - mean, dy = x4.y - mean, dz = x4.z - mean, dw = x4.w - mean;
    red[t] = dx * dx + dy * dy + dz * dz + dw * dw; __syncthreads();
    #pragma unroll
    for (int s = 128; s > 0; s >>= 1) {
        if (t < s) red[t] += red[t + s];
        __syncthreads();
    }
    float rstd = rsqrtf(red[0] * (1.0f / Hv) + 1e-12f);

    float4 gg = *(const float4*)&gam[t * 4];
    float4 bb = *(const float4*)&bet[t * 4];
    float4 out;
    out.x = dx * rstd * gg.x + bb.x;
    out.y = dy * rstd * gg.y + bb.y;
    out.z = dz * rstd * gg.z + bb.z;
    out.w = dw * rstd * gg.w + bb.w;
    *(float4*)&Y[(size_t)row * Hv + t * 4] = out;

    if (Oh) {
        size_t o = (size_t)row * Hv + t * 4;
        __nv_bfloat16 h, l;
        split2(out.x, h, l); Oh[o]     = h; Ol[o]     = l;
        split2(out.y, h, l); Oh[o + 1] = h; Ol[o + 1] = l;
        split2(out.z, h, l); Oh[o + 2] = h; Ol[o + 2] = l;
        split2(out.w, h, l); Oh[o + 3] = h; Ol[o + 3] = l;
    }
}

// ============================================================
// Launch
// ============================================================
extern "C" void kernel_launch(void* const* d_in, const int* in_sizes, int n_in,
                              void* d_out, int out_size)
{
    const float* x    = (const float*)d_in[0];
    const float* mask = (const float*)d_in[1];
    const float* Wq   = (const float*)d_in[2];
    const float* bq   = (const float*)d_in[3];
    const float* Wk   = (const float*)d_in[4];
    const float* bk   = (const float*)d_in[5];
    const float* Wv   = (const float*)d_in[6];
    const float* bv   = (const float*)d_in[7];
    const float* Wo   = (const float*)d_in[8];
    const float* bo   = (const float*)d_in[9];
    const float* ln1g = (const float*)d_in[10];
    const float* ln1b = (const float*)d_in[11];
    const float* W1   = (const float*)d_in[12];
    const float* b1   = (const float*)d_in[13];
    const float* W2   = (const float*)d_in[14];
    const float* b2   = (const float*)d_in[15];
    const float* ln2g = (const float*)d_in[16];
    const float* ln2b = (const float*)d_in[17];
    float* out = (float*)d_out;

    float *q, *k, *v, *res1, *x1, *res2;
    __nv_bfloat16 *ah, *al, *fh, *fl;
    __nv_bfloat16 *wqh, *wql, *wkh, *wkl, *wvh, *wvl, *woh, *wol, *w1h, *w1l, *w2h, *w2l;
    cudaGetSymbolAddress((void**)&q,    g_q);
    cudaGetSymbolAddress((void**)&k,    g_k);
    cudaGetSymbolAddress((void**)&v,    g_v);
    cudaGetSymbolAddress((void**)&res1, g_res1);
    cudaGetSymbolAddress((void**)&x1,   g_x1);
    cudaGetSymbolAddress((void**)&res2, g_res2);
    cudaGetSymbolAddress((void**)&ah,   g_ah);
    cudaGetSymbolAddress((void**)&al,   g_al);
    cudaGetSymbolAddress((void**)&fh,   g_fh);
    cudaGetSymbolAddress((void**)&fl,   g_fl);
    cudaGetSymbolAddress((void**)&wqh,  g_wqh);
    cudaGetSymbolAddress((void**)&wql,  g_wql);
    cudaGetSymbolAddress((void**)&wkh,  g_wkh);
    cudaGetSymbolAddress((void**)&wkl,  g_wkl);
    cudaGetSymbolAddress((void**)&wvh,  g_wvh);
    cudaGetSymbolAddress((void**)&wvl,  g_wvl);
    cudaGetSymbolAddress((void**)&woh,  g_woh);
    cudaGetSymbolAddress((void**)&wol,  g_wol);
    cudaGetSymbolAddress((void**)&w1h,  g_w1h);
    cudaGetSymbolAddress((void**)&w1l,  g_w1l);
    cudaGetSymbolAddress((void**)&w2h,  g_w2h);
    cudaGetSymbolAddress((void**)&w2l,  g_w2l);

    cudaFuncSetAttribute(gemm_mma, cudaFuncAttributeMaxDynamicSharedMemorySize, GSMEM);
    const int attnSmem = 4 * 64 * 65 * sizeof(float);
    cudaFuncSetAttribute(attn_kernel, cudaFuncAttributeMaxDynamicSharedMemorySize, attnSmem);

    dim3 tb(32, 8);
    // weight prep: transpose + split
    transpose_split<<<dim3(Hv/32,  Hv/32),  tb>>>(Wq, wqh, wql, Hv, Hv);
    transpose_split<<<dim3(Hv/32,  Hv/32),  tb>>>(Wk, wkh, wkl, Hv, Hv);
    transpose_split<<<dim3(Hv/32,  Hv/32),  tb>>>(Wv, wvh, wvl, Hv, Hv);
    transpose_split<<<dim3(Hv/32,  Hv/32),  tb>>>(Wo, woh, wol, Hv, Hv);
    transpose_split<<<dim3(FFv/32, Hv/32),  tb>>>(W1, w1h, w1l, Hv, FFv);
    transpose_split<<<dim3(Hv/32,  FFv/32), tb>>>(W2, w2h, w2l, FFv, Hv);
    // input split
    split_k<<<(Mv*Hv)/1024, 256>>>(x, ah, al, Mv*Hv);

    dim3 gH(Hv / 128, Mv / 128);    // (8, 64)
    dim3 gF(FFv / 128, Mv / 128);   // (32, 64)

    // QKV
    gemm_mma<<<gH, 256, GSMEM>>>(ah, al, wqh, wql, bq, nullptr, q, nullptr, nullptr, Hv, Hv, 0);
    gemm_mma<<<gH, 256, GSMEM>>>(ah, al, wkh, wkl, bk, nullptr, k, nullptr, nullptr, Hv, Hv, 0);
    gemm_mma<<<gH, 256, GSMEM>>>(ah, al, wvh, wvl, bv, nullptr, v, nullptr, nullptr, Hv, Hv, 0);

    // attention -> ctx split (into ah/al)
    dim3 gA(Sv / 64, NHv, Bv);
    attn_kernel<<<gA, 256, attnSmem>>>(q, k, v, mask, ah, al);

    // proj + residual, LN1 (-> x1 fp32 + split into ah/al)
    gemm_mma<<<gH, 256, GSMEM>>>(ah, al, woh, wol, bo, x, res1, nullptr, nullptr, Hv, Hv, 0);
    ln_kernel<<<Mv, 256>>>(res1, ln1g, ln1b, x1, ah, al);

    // FFN
    gemm_mma<<<gF, 256, GSMEM>>>(ah, al, w1h, w1l, b1, nullptr, nullptr, fh, fl, Hv, FFv, 1);
    gemm_mma<<<gH, 256, GSMEM>>>(fh, fl, w2h, w2l, b2, x1, res2, nullptr, nullptr, FFv, Hv, 0);
    ln_kernel<<<Mv, 256>>>(res2, ln2g, ln2b, out, nullptr, nullptr);
}

// round 4
// speedup vs baseline: 2.6939x; 1.5201x over previous
#include <cuda_runtime.h>
#include <cuda_bf16.h>
#include <math.h>
#include <stdint.h>

// ---- problem dims ----
#define Bv 4
#define Sv 2048
#define Hv 1024
#define NHv 16
#define HDv 64
#define FFv 4096
#define Mv (Bv*Sv)   // 8192 rows

// ---- scratch (device globals; no allocation allowed) ----
__device__ float g_res1[Mv*Hv];
__device__ float g_x1[Mv*Hv];
__device__ float g_res2[Mv*Hv];

// split activations (x -> [QKV in] ; ctx -> [proj in] ; x1 -> [FF1 in])
__device__ __nv_bfloat16 g_ah[Mv*Hv];
__device__ __nv_bfloat16 g_al[Mv*Hv];
// split QKV
__device__ __nv_bfloat16 g_qh[Mv*Hv], g_ql[Mv*Hv];
__device__ __nv_bfloat16 g_kh[Mv*Hv], g_kl[Mv*Hv];
__device__ __nv_bfloat16 g_vh[Mv*Hv], g_vl[Mv*Hv];
// split FF intermediate
__device__ __nv_bfloat16 g_fh[Mv*FFv];
__device__ __nv_bfloat16 g_fl[Mv*FFv];
// transposed+split weights  (Wt is [N,K] K-major)
__device__ __nv_bfloat16 g_wqh[Hv*Hv], g_wql[Hv*Hv];
__device__ __nv_bfloat16 g_wkh[Hv*Hv], g_wkl[Hv*Hv];
__device__ __nv_bfloat16 g_wvh[Hv*Hv], g_wvl[Hv*Hv];
__device__ __nv_bfloat16 g_woh[Hv*Hv], g_wol[Hv*Hv];
__device__ __nv_bfloat16 g_w1h[FFv*Hv], g_w1l[FFv*Hv];
__device__ __nv_bfloat16 g_w2h[Hv*FFv], g_w2l[Hv*FFv];

// ============================================================
// helpers
// ============================================================
__device__ __forceinline__ uint32_t s2u(const void* p) {
    uint32_t a;
    asm("{ .reg .u64 t; cvta.to.shared.u64 t, %1; cvt.u32.u64 %0, t; }" : "=r"(a) : "l"(p));
    return a;
}
__device__ __forceinline__ void split2(float a, __nv_bfloat16& h, __nv_bfloat16& l) {
    h = __float2bfloat16(a);
    l = __float2bfloat16(a - __bfloat162float(h));
}
__device__ __forceinline__ void cpasync16(uint32_t dst, const void* src) {
    asm volatile("cp.async.cg.shared.global [%0], [%1], 16;" :: "r"(dst), "l"(src));
}
#define CP_COMMIT() asm volatile("cp.async.commit_group;" ::: "memory")
#define CP_WAIT(n)  asm volatile("cp.async.wait_group %0;" :: "n"(n) : "memory")

__device__ __forceinline__ void ldsm4(uint32_t& r0, uint32_t& r1, uint32_t& r2, uint32_t& r3,
                                      uint32_t addr) {
    asm volatile("ldmatrix.sync.aligned.m8n8.x4.shared.b16 {%0,%1,%2,%3}, [%4];"
                 : "=r"(r0), "=r"(r1), "=r"(r2), "=r"(r3) : "r"(addr));
}
__device__ __forceinline__ void ldsm4t(uint32_t& r0, uint32_t& r1, uint32_t& r2, uint32_t& r3,
                                       uint32_t addr) {
    asm volatile("ldmatrix.sync.aligned.m8n8.x4.trans.shared.b16 {%0,%1,%2,%3}, [%4];"
                 : "=r"(r0), "=r"(r1), "=r"(r2), "=r"(r3) : "r"(addr));
}
__device__ __forceinline__ void mma16816(float* d, const uint32_t* a, const uint32_t* b) {
    asm volatile("mma.sync.aligned.m16n8k16.row.col.f32.bf16.bf16.f32 "
                 "{%0,%1,%2,%3}, {%4,%5,%6,%7}, {%8,%9}, {%0,%1,%2,%3};"
                 : "+f"(d[0]), "+f"(d[1]), "+f"(d[2]), "+f"(d[3])
                 : "r"(a[0]), "r"(a[1]), "r"(a[2]), "r"(a[3]), "r"(b[0]), "r"(b[1]));
}
// pack two fp32 -> bf16x2 (lo in low half)
__device__ __forceinline__ uint32_t packbf(float lo, float hi) {
    uint32_t r;
    asm("cvt.rn.bf16x2.f32 %0, %1, %2;" : "=r"(r) : "f"(hi), "f"(lo));
    return r;
}
#define SWZ(o) ((o) ^ (((o) >> 3) & 0x70))

// ============================================================
// Split-bf16 tensor-core GEMM (same as R3, epilogue emits fp32 and/or splits)
// ============================================================
#define BKc 32
#define TILE_BYTES 8192
#define STAGE_BYTES 32768
#define GSMEM 65536

__global__ __launch_bounds__(256) void gemm_mma(
    const __nv_bfloat16* __restrict__ Ah, const __nv_bfloat16* __restrict__ Al,
    const __nv_bfloat16* __restrict__ Bh, const __nv_bfloat16* __restrict__ Bl,
    const float* __restrict__ bias, const float* __restrict__ resid,
    float* __restrict__ C, __nv_bfloat16* __restrict__ Ch, __nv_bfloat16* __restrict__ Cl,
    int K, int N, int act)
{
    extern __shared__ __align__(1024) char smem[];
    uint32_t sb = s2u(smem);
    int t = threadIdx.x, lane = t & 31, warp = t >> 5;
    int wm = warp & 1, wn = warp >> 1;
    int bm = blockIdx.y * 128, bn = blockIdx.x * 128;

    const __nv_bfloat16* srcs[4];
    srcs[0] = Ah + (size_t)bm * K;
    srcs[1] = Al + (size_t)bm * K;
    srcs[2] = Bh + (size_t)bn * K;
    srcs[3] = Bl + (size_t)bn * K;

    float acc[4][4][4];
    #pragma unroll
    for (int i = 0; i < 4; i++)
        #pragma unroll
        for (int j = 0; j < 4; j++)
            #pragma unroll
            for (int e = 0; e < 4; e++) acc[i][j][e] = 0.f;

    int nc = K / BKc;

    auto load_stage = [&](int s, int c) {
        int kb = c * BKc;
        #pragma unroll
        for (int i = 0; i < 8; i++) {
            int idx = i * 256 + t;
            int o   = idx >> 9;
            int rem = idx & 511;
            int r   = rem >> 2;
            int ch  = rem & 3;
            const __nv_bfloat16* src = srcs[o] + (size_t)r * K + kb + ch * 8;
            uint32_t dst = sb + s * STAGE_BYTES + o * TILE_BYTES
                         + r * 64 + ((ch ^ ((r >> 1) & 3)) << 4);
            cpasync16(dst, src);
        }
    };

    load_stage(0, 0);
    CP_COMMIT();

    for (int c = 0; c < nc; c++) {
        int s = c & 1;
        if (c + 1 < nc) {
            load_stage(s ^ 1, c + 1);
            CP_COMMIT();
            CP_WAIT(1);
        } else {
            CP_WAIT(0);
        }
        __syncthreads();

        uint32_t tb = sb + s * STAGE_BYTES;
        int g = lane >> 3;

        #pragma unroll
        for (int ks = 0; ks < 2; ks++) {
            uint32_t aH[4][4], aL[4][4], bH[4][2], bL[4][2];
            {
                int arow_off = ((g & 1) << 3) + (lane & 7);
                int ach = 2 * ks + (g >> 1);
                #pragma unroll
                for (int mf = 0; mf < 4; mf++) {
                    int row = wm * 64 + mf * 16 + arow_off;
                    uint32_t ad = tb + row * 64 + ((ach ^ ((row >> 1) & 3)) << 4);
                    ldsm4(aH[mf][0], aH[mf][1], aH[mf][2], aH[mf][3], ad);
                    ldsm4(aL[mf][0], aL[mf][1], aL[mf][2], aL[mf][3], ad + TILE_BYTES);
                }
            }
            {
                int brow_off = ((g >> 1) << 3) + (lane & 7);
                int bch = 2 * ks + (g & 1);
                #pragma unroll
                for (int np = 0; np < 2; np++) {
                    int row = wn * 32 + np * 16 + brow_off;
                    uint32_t bd = tb + 2 * TILE_BYTES + row * 64
                                + ((bch ^ ((row >> 1) & 3)) << 4);
                    ldsm4(bH[2*np][0], bH[2*np][1], bH[2*np+1][0], bH[2*np+1][1], bd);
                    ldsm4(bL[2*np][0], bL[2*np][1], bL[2*np+1][0], bL[2*np+1][1],
                          bd + TILE_BYTES);
                }
            }
            #pragma unroll
            for (int mf = 0; mf < 4; mf++)
                #pragma unroll
                for (int nf = 0; nf < 4; nf++) {
                    mma16816(acc[mf][nf], aH[mf], bH[nf]);
                    mma16816(acc[mf][nf], aH[mf], bL[nf]);
                    mma16816(acc[mf][nf], aL[mf], bH[nf]);
                }
        }
        __syncthreads();
    }

    #pragma unroll
    for (int mf = 0; mf < 4; mf++) {
        int r0 = bm + wm * 64 + mf * 16 + (lane >> 2);
        #pragma unroll
        for (int nf = 0; nf < 4; nf++) {
            int j = bn + wn * 32 + nf * 8 + (lane & 3) * 2;
            float b0 = bias[j], b1 = bias[j + 1];
            #pragma unroll
            for (int half = 0; half < 2; half++) {
                int row = r0 + half * 8;
                float v0 = acc[mf][nf][half * 2 + 0] + b0;
                float v1 = acc[mf][nf][half * 2 + 1] + b1;
                if (act) {
                    float xg = v0;
                    v0 = 0.5f * xg * (1.0f + tanhf(0.7978845608028654f *
                            (xg + 0.044715f * xg * xg * xg)));
                    xg = v1;
                    v1 = 0.5f * xg * (1.0f + tanhf(0.7978845608028654f *
                            (xg + 0.044715f * xg * xg * xg)));
                }
                size_t o = (size_t)row * N + j;
                if (resid) { v0 += resid[o]; v1 += resid[o + 1]; }
                if (C) { C[o] = v0; C[o + 1] = v1; }
                if (Ch) {
                    __nv_bfloat16 h, l;
                    split2(v0, h, l); Ch[o]     = h; Cl[o]     = l;
                    split2(v1, h, l); Ch[o + 1] = h; Cl[o + 1] = l;
                }
            }
        }
    }
}

// ============================================================
// Tensor-core flash attention, split-bf16 (3-pass both GEMMs).
// CTA: 128 q rows of one (b,h); 8 warps, 16 rows/warp; 64-key tiles.
// smem: Qh,Ql [128][64] bf16 (16KB each) + 2-stage KV (Kh,Kl,Vh,Vl 8KB each).
// ============================================================
#define AQ_BYTES 16384          // one Q tile (128 rows * 128B)
#define AKV_TILE 8192           // one KV tile (64 rows * 128B)
#define AKV_STAGE 32768
#define ASMEM (2*AQ_BYTES + 2*AKV_STAGE)   // 96KB

__global__ __launch_bounds__(256) void attn_mma(
    const __nv_bfloat16* __restrict__ Qh, const __nv_bfloat16* __restrict__ Ql,
    const __nv_bfloat16* __restrict__ Kh, const __nv_bfloat16* __restrict__ Kl,
    const __nv_bfloat16* __restrict__ Vh, const __nv_bfloat16* __restrict__ Vl,
    const float* __restrict__ mask,
    __nv_bfloat16* __restrict__ Oh, __nv_bfloat16* __restrict__ Ol)
{
    extern __shared__ __align__(1024) char smem[];
    uint32_t sb = s2u(smem);
    int t = threadIdx.x, lane = t & 31, warp = t >> 5;
    int qb = blockIdx.x * 128;
    int h  = blockIdx.y;
    int b  = blockIdx.z;
    const size_t bh = (size_t)b * Sv * Hv + (size_t)h * HDv;

    // ---- load Q tiles (group A) ----
    {
        const __nv_bfloat16* qs[2] = { Qh, Ql };
        #pragma unroll
        for (int i = 0; i < 8; i++) {
            int idx = i * 256 + t;            // 0..2047
            int tile = idx >> 10;
            int rem  = idx & 1023;
            int r    = rem >> 3;
            int ch   = rem & 7;
            const __nv_bfloat16* src = qs[tile] + bh + (size_t)(qb + r) * Hv + ch * 8;
            uint32_t dst = sb + tile * AQ_BYTES + SWZ(r * 128 + ch * 16);
            cpasync16(dst, src);
        }
        CP_COMMIT();
    }

    const __nv_bfloat16* kvsrc[4] = { Kh, Kl, Vh, Vl };
    auto load_kv = [&](int s, int kb) {
        #pragma unroll
        for (int i = 0; i < 8; i++) {
            int idx  = i * 256 + t;           // 0..2047
            int tile = idx >> 9;
            int rem  = idx & 511;
            int r    = rem >> 3;
            int ch   = rem & 7;
            const __nv_bfloat16* src = kvsrc[tile] + bh + (size_t)(kb + r) * Hv + ch * 8;
            uint32_t dst = sb + 2 * AQ_BYTES + s * AKV_STAGE + tile * AKV_TILE
                         + SWZ(r * 128 + ch * 16);
            cpasync16(dst, src);
        }
    };

    load_kv(0, 0);
    CP_COMMIT();
    CP_WAIT(1);             // Q arrived
    __syncthreads();

    // ---- preload Q fragments ----
    int g = lane >> 3;
    uint32_t qfh[4][4], qfl[4][4];
    {
        int arow = warp * 16 + ((g & 1) << 3) + (lane & 7);
        #pragma unroll
        for (int ks = 0; ks < 4; ks++) {
            int ach = 2 * ks + (g >> 1);
            uint32_t ad = sb + SWZ(arow * 128 + ach * 16);
            ldsm4(qfh[ks][0], qfh[ks][1], qfh[ks][2], qfh[ks][3], ad);
            ldsm4(qfl[ks][0], qfl[ks][1], qfl[ks][2], qfl[ks][3], ad + AQ_BYTES);
        }
    }

    float oacc[8][4];
    #pragma unroll
    for (int j = 0; j < 8; j++)
        #pragma unroll
        for (int e = 0; e < 4; e++) oacc[j][e] = 0.f;
    float mrow[2] = { -INFINITY, -INFINITY };
    float lrow[2] = { 0.f, 0.f };
    const float* maskRow = mask + (size_t)b * Sv;
    int coff = 2 * (lane & 3);

    for (int it = 0; it < Sv / 64; it++) {
        int s = it & 1;
        if (it + 1 < Sv / 64) {
            load_kv(s ^ 1, (it + 1) * 64);
            CP_COMMIT();
            CP_WAIT(1);
        } else {
            CP_WAIT(0);
        }
        __syncthreads();
        uint32_t stg = sb + 2 * AQ_BYTES + s * AKV_STAGE;

        // ---- scores = Q K^T (3 passes) ----
        float sacc[8][4];
        #pragma unroll
        for (int j = 0; j < 8; j++)
            #pragma unroll
            for (int e = 0; e < 4; e++) sacc[j][e] = 0.f;

        #pragma unroll
        for (int ks = 0; ks < 4; ks++) {
            uint32_t kbh[8][2], kbl[8][2];
            int brow = ((g >> 1) << 3) + (lane & 7);
            int bch  = 2 * ks + (g & 1);
            #pragma unroll
            for (int np = 0; np < 4; np++) {
                int row = np * 16 + brow;
                uint32_t ad = stg + SWZ(row * 128 + bch * 16);
                ldsm4(kbh[2*np][0], kbh[2*np][1], kbh[2*np+1][0], kbh[2*np+1][1], ad);
                ldsm4(kbl[2*np][0], kbl[2*np][1], kbl[2*np+1][0], kbl[2*np+1][1],
                      ad + AKV_TILE);
            }
            #pragma unroll
            for (int j = 0; j < 8; j++) {
                mma16816(sacc[j], qfh[ks], kbh[j]);
                mma16816(sacc[j], qfh[ks], kbl[j]);
                mma16816(sacc[j], qfl[ks], kbh[j]);
            }
        }

        // ---- scale + mask ----
        int kb = it * 64;
        #pragma unroll
        for (int j = 0; j < 8; j++) {
            float mk0 = maskRow[kb + 8 * j + coff];
            float mk1 = maskRow[kb + 8 * j + coff + 1];
            sacc[j][0] = sacc[j][0] * 0.125f + mk0;
            sacc[j][1] = sacc[j][1] * 0.125f + mk1;
            sacc[j][2] = sacc[j][2] * 0.125f + mk0;
            sacc[j][3] = sacc[j][3] * 0.125f + mk1;
        }

        // ---- online softmax (per row-half) ----
        #pragma unroll
        for (int rh = 0; rh < 2; rh++) {
            float rmax = -INFINITY;
            #pragma unroll
            for (int j = 0; j < 8; j++)
                rmax = fmaxf(rmax, fmaxf(sacc[j][2*rh], sacc[j][2*rh + 1]));
            rmax = fmaxf(rmax, __shfl_xor_sync(0xffffffffu, rmax, 1));
            rmax = fmaxf(rmax, __shfl_xor_sync(0xffffffffu, rmax, 2));
            float mn   = fmaxf(mrow[rh], rmax);
            float corr = __expf(mrow[rh] - mn);
            float rsum = 0.f;
            #pragma unroll
            for (int j = 0; j < 8; j++) {
                float p0 = __expf(sacc[j][2*rh]     - mn);
                float p1 = __expf(sacc[j][2*rh + 1] - mn);
                sacc[j][2*rh] = p0; sacc[j][2*rh + 1] = p1;
                rsum += p0 + p1;
            }
            rsum += __shfl_xor_sync(0xffffffffu, rsum, 1);
            rsum += __shfl_xor_sync(0xffffffffu, rsum, 2);
            lrow[rh] = lrow[rh] * corr + rsum;
            mrow[rh] = mn;
            #pragma unroll
            for (int j = 0; j < 8; j++) {
                oacc[j][2*rh]     *= corr;
                oacc[j][2*rh + 1] *= corr;
            }
        }

        // ---- O += P V (3 passes, P split in registers) ----
        int vkey0  = ((lane >> 3) & 1) * 8 + (lane & 7);
        int vbyte0 = ((lane >> 4) & 1) * 16;
        #pragma unroll
        for (int ks = 0; ks < 4; ks++) {
            uint32_t aPh[4], aPl[4];
            #pragma unroll
            for (int q4 = 0; q4 < 4; q4++) {
                int jj = 2 * ks + (q4 >> 1);
                float p0 = sacc[jj][(q4 & 1) * 2 + 0];
                float p1 = sacc[jj][(q4 & 1) * 2 + 1];
                float h0 = __bfloat162float(__float2bfloat16(p0));
                float h1 = __bfloat162float(__float2bfloat16(p1));
                aPh[q4] = packbf(h0, h1);
                aPl[q4] = packbf(p0 - h0, p1 - h1);
            }
            // reorder: aP[0]=row/k, aP[1]=row+8/k, aP[2]=row/k+8, aP[3]=row+8/k+8
            // built above as q4: 0->(j=2ks,c01)=a0, 1->(j=2ks,c23)=a1,
            //                    2->(j=2ks+1,c01)=a2, 3->(j=2ks+1,c23)=a3  ✓
            uint32_t vbh[8][2], vbl[8][2];
            int vkey = 16 * ks + vkey0;
            #pragma unroll
            for (int np = 0; np < 4; np++) {
                uint32_t ad = stg + 2 * AKV_TILE + SWZ(vkey * 128 + 32 * np + vbyte0);
                ldsm4t(vbh[2*np][0], vbh[2*np][1], vbh[2*np+1][0], vbh[2*np+1][1], ad);
                ldsm4t(vbl[2*np][0], vbl[2*np][1], vbl[2*np+1][0], vbl[2*np+1][1],
                       ad + AKV_TILE);
            }
            #pragma unroll
            for (int j = 0; j < 8; j++) {
                mma16816(oacc[j], aPh, vbh[j]);
                mma16816(oacc[j], aPh, vbl[j]);
                mma16816(oacc[j], aPl, vbh[j]);
            }
        }
        __syncthreads();
    }

    // ---- write ctx as split bf16 ----
    #pragma unroll
    for (int rh = 0; rh < 2; rh++) {
        float inv = 1.0f / lrow[rh];
        int row = qb + warp * 16 + (lane >> 2) + 8 * rh;
        #pragma unroll
        for (int j = 0; j < 8; j++) {
            float v0 = oacc[j][2*rh]     * inv;
            float v1 = oacc[j][2*rh + 1] * inv;
            __nv_bfloat16 h0, l0, h1, l1;
            split2(v0, h0, l0);
            split2(v1, h1, l1);
            size_t o = bh + (size_t)row * Hv + 8 * j + coff;
            *(__nv_bfloat162*)&Oh[o] = __nv_bfloat162{h0, h1};
            *(__nv_bfloat162*)&Ol[o] = __nv_bfloat162{l0, l1};
        }
    }
}

// ============================================================
// split: fp32 -> (hi, lo) bf16
// ============================================================
__global__ __launch_bounds__(256) void split_k(
    const float* __restrict__ X, __nv_bfloat16* __restrict__ H,
    __nv_bfloat16* __restrict__ L, int n)
{
    int i = (blockIdx.x * 256 + threadIdx.x) * 4;
    if (i >= n) return;
    float4 x4 = *(const float4*)&X[i];
    __nv_bfloat16 h0, l0, h1, l1, h2, l2, h3, l3;
    split2(x4.x, h0, l0); split2(x4.y, h1, l1);
    split2(x4.z, h2, l2); split2(x4.w, h3, l3);
    H[i] = h0; H[i + 1] = h1; H[i + 2] = h2; H[i + 3] = h3;
    L[i] = l0; L[i + 1] = l1; L[i + 2] = l2; L[i + 3] = l3;
}

// ============================================================
// transpose + split: W[K,N] fp32 -> T[N,K] bf16 hi/lo
// ============================================================
__global__ void transpose_split(const float* __restrict__ W,
                                __nv_bfloat16* __restrict__ Th,
                                __nv_bfloat16* __restrict__ Tl, int K, int N)
{
    __shared__ float tile[32][33];
    int bx = blockIdx.x * 32;
    int by = blockIdx.y * 32;
    int tx = threadIdx.x, ty = threadIdx.y;
    #pragma unroll
    for (int j = 0; j < 32; j += 8)
        tile[ty + j][tx] = W[(size_t)(by + ty + j) * N + bx + tx];
    __syncthreads();
    #pragma unroll
    for (int j = 0; j < 32; j += 8) {
        float v = tile[tx][ty + j];
        __nv_bfloat16 h, l;
        split2(v, h, l);
        size_t o = (size_t)(bx + ty + j) * K + by + tx;
        Th[o] = h; Tl[o] = l;
    }
}

// ============================================================
// LayerNorm; optionally also emits bf16 hi/lo splits.
// ============================================================
__global__ __launch_bounds__(256) void ln_kernel(
    const float* __restrict__ X, const float* __restrict__ gam,
    const float* __restrict__ bet, float* __restrict__ Y,
    __nv_bfloat16* __restrict__ Oh, __nv_bfloat16* __restrict__ Ol)
{
    __shared__ float red[256];
    int row = blockIdx.x;
    int t   = threadIdx.x;
    const float* xr = X + (size_t)row * Hv;

    float4 x4 = *(const float4*)&xr[t * 4];
    red[t] = x4.x + x4.y + x4.z + x4.w; __syncthreads();
    #pragma unroll
    for (int s = 128; s > 0; s >>= 1) {
        if (t < s) red[t] += red[t + s];
        __syncthreads();
    }
    float mean = red[0] * (1.0f / Hv);
    __syncthreads();

    float dx = x4.x - mean, dy = x4.y - mean, dz = x4.z - mean, dw = x4.w - mean;
    red[t] = dx * dx + dy * dy + dz * dz + dw * dw; __syncthreads();
    #pragma unroll
    for (int s = 128; s > 0; s >>= 1) {
        if (t < s) red[t] += red[t + s];
        __syncthreads();
    }
    float rstd = rsqrtf(red[0] * (1.0f / Hv) + 1e-12f);

    float4 gg = *(const float4*)&gam[t * 4];
    float4 bb = *(const float4*)&bet[t * 4];
    float4 out;
    out.x = dx * rstd * gg.x + bb.x;
    out.y = dy * rstd * gg.y + bb.y;
    out.z = dz * rstd * gg.z + bb.z;
    out.w = dw * rstd * gg.w + bb.w;
    *(float4*)&Y[(size_t)row * Hv + t * 4] = out;

    if (Oh) {
        size_t o = (size_t)row * Hv + t * 4;
        __nv_bfloat16 h, l;
        split2(out.x, h, l); Oh[o]     = h; Ol[o]     = l;
        split2(out.y, h, l); Oh[o + 1] = h; Ol[o + 1] = l;
        split2(out.z, h, l); Oh[o + 2] = h; Ol[o + 2] = l;
        split2(out.w, h, l); Oh[o + 3] = h; Ol[o + 3] = l;
    }
}

// ============================================================
// Launch
// ============================================================
extern "C" void kernel_launch(void* const* d_in, const int* in_sizes, int n_in,
                              void* d_out, int out_size)
{
    const float* x    = (const float*)d_in[0];
    const float* mask = (const float*)d_in[1];
    const float* Wq   = (const float*)d_in[2];
    const float* bq   = (const float*)d_in[3];
    const float* Wk   = (const float*)d_in[4];
    const float* bk   = (const float*)d_in[5];
    const float* Wv   = (const float*)d_in[6];
    const float* bv   = (const float*)d_in[7];
    const float* Wo   = (const float*)d_in[8];
    const float* bo   = (const float*)d_in[9];
    const float* ln1g = (const float*)d_in[10];
    const float* ln1b = (const float*)d_in[11];
    const float* W1   = (const float*)d_in[12];
    const float* b1   = (const float*)d_in[13];
    const float* W2   = (const float*)d_in[14];
    const float* b2   = (const float*)d_in[15];
    const float* ln2g = (const float*)d_in[16];
    const float* ln2b = (const float*)d_in[17];
    float* out = (float*)d_out;

    float *res1, *x1, *res2;
    __nv_bfloat16 *ah, *al, *fh, *fl;
    __nv_bfloat16 *qh, *ql, *kh, *kl, *vh, *vl;
    __nv_bfloat16 *wqh, *wql, *wkh, *wkl, *wvh, *wvl, *woh, *wol, *w1h, *w1l, *w2h, *w2l;
    cudaGetSymbolAddress((void**)&res1, g_res1);
    cudaGetSymbolAddress((void**)&x1,   g_x1);
    cudaGetSymbolAddress((void**)&res2, g_res2);
    cudaGetSymbolAddress((void**)&ah,   g_ah);
    cudaGetSymbolAddress((void**)&al,   g_al);
    cudaGetSymbolAddress((void**)&fh,   g_fh);
    cudaGetSymbolAddress((void**)&fl,   g_fl);
    cudaGetSymbolAddress((void**)&qh,   g_qh);
    cudaGetSymbolAddress((void**)&ql,   g_ql);
    cudaGetSymbolAddress((void**)&kh,   g_kh);
    cudaGetSymbolAddress((void**)&kl,   g_kl);
    cudaGetSymbolAddress((void**)&vh,   g_vh);
    cudaGetSymbolAddress((void**)&vl,   g_vl);
    cudaGetSymbolAddress((void**)&wqh,  g_wqh);
    cudaGetSymbolAddress((void**)&wql,  g_wql);
    cudaGetSymbolAddress((void**)&wkh,  g_wkh);
    cudaGetSymbolAddress((void**)&wkl,  g_wkl);
    cudaGetSymbolAddress((void**)&wvh,  g_wvh);
    cudaGetSymbolAddress((void**)&wvl,  g_wvl);
    cudaGetSymbolAddress((void**)&woh,  g_woh);
    cudaGetSymbolAddress((void**)&wol,  g_wol);
    cudaGetSymbolAddress((void**)&w1h,  g_w1h);
    cudaGetSymbolAddress((void**)&w1l,  g_w1l);
    cudaGetSymbolAddress((void**)&w2h,  g_w2h);
    cudaGetSymbolAddress((void**)&w2l,  g_w2l);

    cudaFuncSetAttribute(gemm_mma, cudaFuncAttributeMaxDynamicSharedMemorySize, GSMEM);
    cudaFuncSetAttribute(attn_mma, cudaFuncAttributeMaxDynamicSharedMemorySize, ASMEM);

    dim3 tb(32, 8);
    transpose_split<<<dim3(Hv/32,  Hv/32),  tb>>>(Wq, wqh, wql, Hv, Hv);
    transpose_split<<<dim3(Hv/32,  Hv/32),  tb>>>(Wk, wkh, wkl, Hv, Hv);
    transpose_split<<<dim3(Hv/32,  Hv/32),  tb>>>(Wv, wvh, wvl, Hv, Hv);
    transpose_split<<<dim3(Hv/32,  Hv/32),  tb>>>(Wo, woh, wol, Hv, Hv);
    transpose_split<<<dim3(FFv/32, Hv/32),  tb>>>(W1, w1h, w1l, Hv, FFv);
    transpose_split<<<dim3(Hv/32,  FFv/32), tb>>>(W2, w2h, w2l, FFv, Hv);
    split_k<<<(Mv*Hv)/1024, 256>>>(x, ah, al, Mv*Hv);

    dim3 gH(Hv / 128, Mv / 128);
    dim3 gF(FFv / 128, Mv / 128);

    // QKV -> split bf16 directly
    gemm_mma<<<gH, 256, GSMEM>>>(ah, al, wqh, wql, bq, nullptr, nullptr, qh, ql, Hv, Hv, 0);
    gemm_mma<<<gH, 256, GSMEM>>>(ah, al, wkh, wkl, bk, nullptr, nullptr, kh, kl, Hv, Hv, 0);
    gemm_mma<<<gH, 256, GSMEM>>>(ah, al, wvh, wvl, bv, nullptr, nullptr, vh, vl, Hv, Hv, 0);

    // tensor-core flash attention -> ctx split (into ah/al)
    dim3 gA(Sv / 128, NHv, Bv);
    attn_mma<<<gA, 256, ASMEM>>>(qh, ql, kh, kl, vh, vl, mask, ah, al);

    // proj + residual, LN1 (-> x1 fp32 + split into ah/al)
    gemm_mma<<<gH, 256, GSMEM>>>(ah, al, woh, wol, bo, x, res1, nullptr, nullptr, Hv, Hv, 0);
    ln_kernel<<<Mv, 256>>>(res1, ln1g, ln1b, x1, ah, al);

    // FFN
    gemm_mma<<<gF, 256, GSMEM>>>(ah, al, w1h, w1l, b1, nullptr, nullptr, fh, fl, Hv, FFv, 1);
    gemm_mma<<<gH, 256, GSMEM>>>(fh, fl, w2h, w2l, b2, x1, res2, nullptr, nullptr, FFv, Hv, 0);
    ln_kernel<<<Mv, 256>>>(res2, ln2g, ln2b, out, nullptr, nullptr);
}

// round 5
// speedup vs baseline: 2.7244x; 1.0113x over previous
#include <cuda_runtime.h>
#include <cuda_bf16.h>
#include <math.h>
#include <stdint.h>

// ---- problem dims ----
#define Bv 4
#define Sv 2048
#define Hv 1024
#define NHv 16
#define HDv 64
#define FFv 4096
#define Mv (Bv*Sv)   // 8192 rows

// ---- scratch (device globals; no allocation allowed) ----
__device__ float g_res1[Mv*Hv];
__device__ float g_x1[Mv*Hv];
__device__ float g_res2[Mv*Hv];

__device__ __nv_bfloat16 g_ah[Mv*Hv];
__device__ __nv_bfloat16 g_al[Mv*Hv];
__device__ __nv_bfloat16 g_qh[Mv*Hv], g_ql[Mv*Hv];
__device__ __nv_bfloat16 g_kh[Mv*Hv], g_kl[Mv*Hv];
__device__ __nv_bfloat16 g_vh[Mv*Hv], g_vl[Mv*Hv];
__device__ __nv_bfloat16 g_fh[Mv*FFv];
__device__ __nv_bfloat16 g_fl[Mv*FFv];
__device__ __nv_bfloat16 g_wqh[Hv*Hv], g_wql[Hv*Hv];
__device__ __nv_bfloat16 g_wkh[Hv*Hv], g_wkl[Hv*Hv];
__device__ __nv_bfloat16 g_wvh[Hv*Hv], g_wvl[Hv*Hv];
__device__ __nv_bfloat16 g_woh[Hv*Hv], g_wol[Hv*Hv];
__device__ __nv_bfloat16 g_w1h[FFv*Hv], g_w1l[FFv*Hv];
__device__ __nv_bfloat16 g_w2h[Hv*FFv], g_w2l[Hv*FFv];

// ============================================================
// helpers
// ============================================================
__device__ __forceinline__ uint32_t s2u(const void* p) {
    uint32_t a;
    asm("{ .reg .u64 t; cvta.to.shared.u64 t, %1; cvt.u32.u64 %0, t; }" : "=r"(a) : "l"(p));
    return a;
}
__device__ __forceinline__ void split2(float a, __nv_bfloat16& h, __nv_bfloat16& l) {
    h = __float2bfloat16(a);
    l = __float2bfloat16(a - __bfloat162float(h));
}
__device__ __forceinline__ void cpasync16(uint32_t dst, const void* src) {
    asm volatile("cp.async.cg.shared.global [%0], [%1], 16;" :: "r"(dst), "l"(src));
}
#define CP_COMMIT() asm volatile("cp.async.commit_group;" ::: "memory")
#define CP_WAIT(n)  asm volatile("cp.async.wait_group %0;" :: "n"(n) : "memory")

__device__ __forceinline__ void ldsm4(uint32_t& r0, uint32_t& r1, uint32_t& r2, uint32_t& r3,
                                      uint32_t addr) {
    asm volatile("ldmatrix.sync.aligned.m8n8.x4.shared.b16 {%0,%1,%2,%3}, [%4];"
                 : "=r"(r0), "=r"(r1), "=r"(r2), "=r"(r3) : "r"(addr));
}
__device__ __forceinline__ void ldsm4t(uint32_t& r0, uint32_t& r1, uint32_t& r2, uint32_t& r3,
                                       uint32_t addr) {
    asm volatile("ldmatrix.sync.aligned.m8n8.x4.trans.shared.b16 {%0,%1,%2,%3}, [%4];"
                 : "=r"(r0), "=r"(r1), "=r"(r2), "=r"(r3) : "r"(addr));
}
__device__ __forceinline__ void mma16816(float* d, const uint32_t* a, const uint32_t* b) {
    asm volatile("mma.sync.aligned.m16n8k16.row.col.f32.bf16.bf16.f32 "
                 "{%0,%1,%2,%3}, {%4,%5,%6,%7}, {%8,%9}, {%0,%1,%2,%3};"
                 : "+f"(d[0]), "+f"(d[1]), "+f"(d[2]), "+f"(d[3])
                 : "r"(a[0]), "r"(a[1]), "r"(a[2]), "r"(a[3]), "r"(b[0]), "r"(b[1]));
}
__device__ __forceinline__ uint32_t packbf(float lo, float hi) {
    uint32_t r;
    asm("cvt.rn.bf16x2.f32 %0, %1, %2;" : "=r"(r) : "f"(hi), "f"(lo));
    return r;
}
#define SWZ(o) ((o) ^ (((o) >> 3) & 0x70))

// ============================================================
// Split-bf16 tensor-core GEMM, 4-stage cp.async pipeline.
// ============================================================
#define BKc 32
#define TILE_BYTES 8192
#define STAGE_BYTES 32768
#define GSMEM (4*STAGE_BYTES)    // 128KB

__global__ __launch_bounds__(256) void gemm_mma(
    const __nv_bfloat16* __restrict__ Ah, const __nv_bfloat16* __restrict__ Al,
    const __nv_bfloat16* __restrict__ Bh, const __nv_bfloat16* __restrict__ Bl,
    const float* __restrict__ bias, const float* __restrict__ resid,
    float* __restrict__ C, __nv_bfloat16* __restrict__ Ch, __nv_bfloat16* __restrict__ Cl,
    int K, int N, int act)
{
    extern __shared__ __align__(1024) char smem[];
    uint32_t sb = s2u(smem);
    int t = threadIdx.x, lane = t & 31, warp = t >> 5;
    int wm = warp & 1, wn = warp >> 1;
    int bm = blockIdx.y * 128, bn = blockIdx.x * 128;

    const __nv_bfloat16* srcs[4];
    srcs[0] = Ah + (size_t)bm * K;
    srcs[1] = Al + (size_t)bm * K;
    srcs[2] = Bh + (size_t)bn * K;
    srcs[3] = Bl + (size_t)bn * K;

    float acc[4][4][4];
    #pragma unroll
    for (int i = 0; i < 4; i++)
        #pragma unroll
        for (int j = 0; j < 4; j++)
            #pragma unroll
            for (int e = 0; e < 4; e++) acc[i][j][e] = 0.f;

    int nc = K / BKc;

    auto load_stage = [&](int s, int c) {
        int kb = c * BKc;
        #pragma unroll
        for (int i = 0; i < 8; i++) {
            int idx = i * 256 + t;
            int o   = idx >> 9;
            int rem = idx & 511;
            int r   = rem >> 2;
            int ch  = rem & 3;
            const __nv_bfloat16* src = srcs[o] + (size_t)r * K + kb + ch * 8;
            uint32_t dst = sb + s * STAGE_BYTES + o * TILE_BYTES
                         + r * 64 + ((ch ^ ((r >> 1) & 3)) << 4);
            cpasync16(dst, src);
        }
    };

    // prologue: fill 3 stages
    #pragma unroll
    for (int i = 0; i < 3; i++) { load_stage(i, i); CP_COMMIT(); }

    for (int c = 0; c < nc; c++) {
        CP_WAIT(2);          // chunk c landed
        __syncthreads();     // publish chunk c; all warps done with chunk c-1's buffer
        if (c + 3 < nc) { load_stage((c + 3) & 3, c + 3); CP_COMMIT(); }

        uint32_t tb = sb + (c & 3) * STAGE_BYTES;
        int g = lane >> 3;

        #pragma unroll
        for (int ks = 0; ks < 2; ks++) {
            uint32_t aH[4][4], aL[4][4], bH[4][2], bL[4][2];
            {
                int arow_off = ((g & 1) << 3) + (lane & 7);
                int ach = 2 * ks + (g >> 1);
                #pragma unroll
                for (int mf = 0; mf < 4; mf++) {
                    int row = wm * 64 + mf * 16 + arow_off;
                    uint32_t ad = tb + row * 64 + ((ach ^ ((row >> 1) & 3)) << 4);
                    ldsm4(aH[mf][0], aH[mf][1], aH[mf][2], aH[mf][3], ad);
                    ldsm4(aL[mf][0], aL[mf][1], aL[mf][2], aL[mf][3], ad + TILE_BYTES);
                }
            }
            {
                int brow_off = ((g >> 1) << 3) + (lane & 7);
                int bch = 2 * ks + (g & 1);
                #pragma unroll
                for (int np = 0; np < 2; np++) {
                    int row = wn * 32 + np * 16 + brow_off;
                    uint32_t bd = tb + 2 * TILE_BYTES + row * 64
                                + ((bch ^ ((row >> 1) & 3)) << 4);
                    ldsm4(bH[2*np][0], bH[2*np][1], bH[2*np+1][0], bH[2*np+1][1], bd);
                    ldsm4(bL[2*np][0], bL[2*np][1], bL[2*np+1][0], bL[2*np+1][1],
                          bd + TILE_BYTES);
                }
            }
            #pragma unroll
            for (int mf = 0; mf < 4; mf++)
                #pragma unroll
                for (int nf = 0; nf < 4; nf++) {
                    mma16816(acc[mf][nf], aH[mf], bH[nf]);
                    mma16816(acc[mf][nf], aH[mf], bL[nf]);
                    mma16816(acc[mf][nf], aL[mf], bH[nf]);
                }
        }
    }

    #pragma unroll
    for (int mf = 0; mf < 4; mf++) {
        int r0 = bm + wm * 64 + mf * 16 + (lane >> 2);
        #pragma unroll
        for (int nf = 0; nf < 4; nf++) {
            int j = bn + wn * 32 + nf * 8 + (lane & 3) * 2;
            float b0 = bias[j], b1 = bias[j + 1];
            #pragma unroll
            for (int half = 0; half < 2; half++) {
                int row = r0 + half * 8;
                float v0 = acc[mf][nf][half * 2 + 0] + b0;
                float v1 = acc[mf][nf][half * 2 + 1] + b1;
                if (act) {
                    float xg = v0;
                    v0 = 0.5f * xg * (1.0f + tanhf(0.7978845608028654f *
                            (xg + 0.044715f * xg * xg * xg)));
                    xg = v1;
                    v1 = 0.5f * xg * (1.0f + tanhf(0.7978845608028654f *
                            (xg + 0.044715f * xg * xg * xg)));
                }
                size_t o = (size_t)row * N + j;
                if (resid) { v0 += resid[o]; v1 += resid[o + 1]; }
                if (C) { C[o] = v0; C[o + 1] = v1; }
                if (Ch) {
                    __nv_bfloat16 h, l;
                    split2(v0, h, l); Ch[o]     = h; Cl[o]     = l;
                    split2(v1, h, l); Ch[o + 1] = h; Cl[o + 1] = l;
                }
            }
        }
    }
}

// ============================================================
// Tensor-core flash attention, split-bf16, 3-stage KV pipeline.
// ============================================================
#define AQ_BYTES 16384
#define AKV_TILE 8192
#define AKV_STAGE 32768
#define ASMEM (2*AQ_BYTES + 3*AKV_STAGE)   // 128KB

__global__ __launch_bounds__(256) void attn_mma(
    const __nv_bfloat16* __restrict__ Qh, const __nv_bfloat16* __restrict__ Ql,
    const __nv_bfloat16* __restrict__ Kh, const __nv_bfloat16* __restrict__ Kl,
    const __nv_bfloat16* __restrict__ Vh, const __nv_bfloat16* __restrict__ Vl,
    const float* __restrict__ mask,
    __nv_bfloat16* __restrict__ Oh, __nv_bfloat16* __restrict__ Ol)
{
    extern __shared__ __align__(1024) char smem[];
    uint32_t sb = s2u(smem);
    int t = threadIdx.x, lane = t & 31, warp = t >> 5;
    int qb = blockIdx.x * 128;
    int h  = blockIdx.y;
    int b  = blockIdx.z;
    const size_t bh = (size_t)b * Sv * Hv + (size_t)h * HDv;

    // ---- load Q tiles ----
    {
        const __nv_bfloat16* qs[2] = { Qh, Ql };
        #pragma unroll
        for (int i = 0; i < 8; i++) {
            int idx = i * 256 + t;
            int tile = idx >> 10;
            int rem  = idx & 1023;
            int r    = rem >> 3;
            int ch   = rem & 7;
            const __nv_bfloat16* src = qs[tile] + bh + (size_t)(qb + r) * Hv + ch * 8;
            uint32_t dst = sb + tile * AQ_BYTES + SWZ(r * 128 + ch * 16);
            cpasync16(dst, src);
        }
        CP_COMMIT();
    }

    const __nv_bfloat16* kvsrc[4] = { Kh, Kl, Vh, Vl };
    auto load_kv = [&](int s, int kb) {
        #pragma unroll
        for (int i = 0; i < 8; i++) {
            int idx  = i * 256 + t;
            int tile = idx >> 9;
            int rem  = idx & 511;
            int r    = rem >> 3;
            int ch   = rem & 7;
            const __nv_bfloat16* src = kvsrc[tile] + bh + (size_t)(kb + r) * Hv + ch * 8;
            uint32_t dst = sb + 2 * AQ_BYTES + s * AKV_STAGE + tile * AKV_TILE
                         + SWZ(r * 128 + ch * 16);
            cpasync16(dst, src);
        }
    };

    // prologue: 2 KV stages in flight
    load_kv(0, 0);  CP_COMMIT();
    load_kv(1, 64); CP_COMMIT();
    CP_WAIT(2);             // Q arrived
    __syncthreads();

    // ---- preload Q fragments ----
    int g = lane >> 3;
    uint32_t qfh[4][4], qfl[4][4];
    {
        int arow = warp * 16 + ((g & 1) << 3) + (lane & 7);
        #pragma unroll
        for (int ks = 0; ks < 4; ks++) {
            int ach = 2 * ks + (g >> 1);
            uint32_t ad = sb + SWZ(arow * 128 + ach * 16);
            ldsm4(qfh[ks][0], qfh[ks][1], qfh[ks][2], qfh[ks][3], ad);
            ldsm4(qfl[ks][0], qfl[ks][1], qfl[ks][2], qfl[ks][3], ad + AQ_BYTES);
        }
    }

    float oacc[8][4];
    #pragma unroll
    for (int j = 0; j < 8; j++)
        #pragma unroll
        for (int e = 0; e < 4; e++) oacc[j][e] = 0.f;
    float mrow[2] = { -INFINITY, -INFINITY };
    float lrow[2] = { 0.f, 0.f };
    const float* maskRow = mask + (size_t)b * Sv;
    int coff = 2 * (lane & 3);

    const int NIT = Sv / 64;
    for (int it = 0; it < NIT; it++) {
        CP_WAIT(1);          // KV chunk `it` landed
        __syncthreads();
        if (it + 2 < NIT) { load_kv((it + 2) % 3, (it + 2) * 64); CP_COMMIT(); }
        uint32_t stg = sb + 2 * AQ_BYTES + (it % 3) * AKV_STAGE;

        // ---- scores = Q K^T (3 passes) ----
        float sacc[8][4];
        #pragma unroll
        for (int j = 0; j < 8; j++)
            #pragma unroll
            for (int e = 0; e < 4; e++) sacc[j][e] = 0.f;

        #pragma unroll
        for (int ks = 0; ks < 4; ks++) {
            uint32_t kbh[8][2], kbl[8][2];
            int brow = ((g >> 1) << 3) + (lane & 7);
            int bch  = 2 * ks + (g & 1);
            #pragma unroll
            for (int np = 0; np < 4; np++) {
                int row = np * 16 + brow;
                uint32_t ad = stg + SWZ(row * 128 + bch * 16);
                ldsm4(kbh[2*np][0], kbh[2*np][1], kbh[2*np+1][0], kbh[2*np+1][1], ad);
                ldsm4(kbl[2*np][0], kbl[2*np][1], kbl[2*np+1][0], kbl[2*np+1][1],
                      ad + AKV_TILE);
            }
            #pragma unroll
            for (int j = 0; j < 8; j++) {
                mma16816(sacc[j], qfh[ks], kbh[j]);
                mma16816(sacc[j], qfh[ks], kbl[j]);
                mma16816(sacc[j], qfl[ks], kbh[j]);
            }
        }

        int kb = it * 64;
        #pragma unroll
        for (int j = 0; j < 8; j++) {
            float mk0 = maskRow[kb + 8 * j + coff];
            float mk1 = maskRow[kb + 8 * j + coff + 1];
            sacc[j][0] = sacc[j][0] * 0.125f + mk0;
            sacc[j][1] = sacc[j][1] * 0.125f + mk1;
            sacc[j][2] = sacc[j][2] * 0.125f + mk0;
            sacc[j][3] = sacc[j][3] * 0.125f + mk1;
        }

        #pragma unroll
        for (int rh = 0; rh < 2; rh++) {
            float rmax = -INFINITY;
            #pragma unroll
            for (int j = 0; j < 8; j++)
                rmax = fmaxf(rmax, fmaxf(sacc[j][2*rh], sacc[j][2*rh + 1]));
            rmax = fmaxf(rmax, __shfl_xor_sync(0xffffffffu, rmax, 1));
            rmax = fmaxf(rmax, __shfl_xor_sync(0xffffffffu, rmax, 2));
            float mn   = fmaxf(mrow[rh], rmax);
            float corr = __expf(mrow[rh] - mn);
            float rsum = 0.f;
            #pragma unroll
            for (int j = 0; j < 8; j++) {
                float p0 = __expf(sacc[j][2*rh]     - mn);
                float p1 = __expf(sacc[j][2*rh + 1] - mn);
                sacc[j][2*rh] = p0; sacc[j][2*rh + 1] = p1;
                rsum += p0 + p1;
            }
            rsum += __shfl_xor_sync(0xffffffffu, rsum, 1);
            rsum += __shfl_xor_sync(0xffffffffu, rsum, 2);
            lrow[rh] = lrow[rh] * corr + rsum;
            mrow[rh] = mn;
            #pragma unroll
            for (int j = 0; j < 8; j++) {
                oacc[j][2*rh]     *= corr;
                oacc[j][2*rh + 1] *= corr;
            }
        }

        // ---- O += P V (3 passes, P split in registers) ----
        int vkey0  = ((lane >> 3) & 1) * 8 + (lane & 7);
        int vbyte0 = ((lane >> 4) & 1) * 16;
        #pragma unroll
        for (int ks = 0; ks < 4; ks++) {
            uint32_t aPh[4], aPl[4];
            #pragma unroll
            for (int q4 = 0; q4 < 4; q4++) {
                int jj = 2 * ks + (q4 >> 1);
                float p0 = sacc[jj][(q4 & 1) * 2 + 0];
                float p1 = sacc[jj][(q4 & 1) * 2 + 1];
                float h0 = __bfloat162float(__float2bfloat16(p0));
                float h1 = __bfloat162float(__float2bfloat16(p1));
                aPh[q4] = packbf(h0, h1);
                aPl[q4] = packbf(p0 - h0, p1 - h1);
            }
            uint32_t vbh[8][2], vbl[8][2];
            int vkey = 16 * ks + vkey0;
            #pragma unroll
            for (int np = 0; np < 4; np++) {
                uint32_t ad = stg + 2 * AKV_TILE + SWZ(vkey * 128 + 32 * np + vbyte0);
                ldsm4t(vbh[2*np][0], vbh[2*np][1], vbh[2*np+1][0], vbh[2*np+1][1], ad);
                ldsm4t(vbl[2*np][0], vbl[2*np][1], vbl[2*np+1][0], vbl[2*np+1][1],
                       ad + AKV_TILE);
            }
            #pragma unroll
            for (int j = 0; j < 8; j++) {
                mma16816(oacc[j], aPh, vbh[j]);
                mma16816(oacc[j], aPh, vbl[j]);
                mma16816(oacc[j], aPl, vbh[j]);
            }
        }
    }

    #pragma unroll
    for (int rh = 0; rh < 2; rh++) {
        float inv = 1.0f / lrow[rh];
        int row = qb + warp * 16 + (lane >> 2) + 8 * rh;
        #pragma unroll
        for (int j = 0; j < 8; j++) {
            float v0 = oacc[j][2*rh]     * inv;
            float v1 = oacc[j][2*rh + 1] * inv;
            __nv_bfloat16 h0, l0, h1, l1;
            split2(v0, h0, l0);
            split2(v1, h1, l1);
            size_t o = bh + (size_t)row * Hv + 8 * j + coff;
            *(__nv_bfloat162*)&Oh[o] = __nv_bfloat162{h0, h1};
            *(__nv_bfloat162*)&Ol[o] = __nv_bfloat162{l0, l1};
        }
    }
}

// ============================================================
// split: fp32 -> (hi, lo) bf16
// ============================================================
__global__ __launch_bounds__(256) void split_k(
    const float* __restrict__ X, __nv_bfloat16* __restrict__ H,
    __nv_bfloat16* __restrict__ L, int n)
{
    int i = (blockIdx.x * 256 + threadIdx.x) * 4;
    if (i >= n) return;
    float4 x4 = *(const float4*)&X[i];
    __nv_bfloat16 h0, l0, h1, l1, h2, l2, h3, l3;
    split2(x4.x, h0, l0); split2(x4.y, h1, l1);
    split2(x4.z, h2, l2); split2(x4.w, h3, l3);
    H[i] = h0; H[i + 1] = h1; H[i + 2] = h2; H[i + 3] = h3;
    L[i] = l0; L[i + 1] = l1; L[i + 2] = l2; L[i + 3] = l3;
}

// ============================================================
// transpose + split: W[K,N] fp32 -> T[N,K] bf16 hi/lo
// ============================================================
__global__ void transpose_split(const float* __restrict__ W,
                                __nv_bfloat16* __restrict__ Th,
                                __nv_bfloat16* __restrict__ Tl, int K, int N)
{
    __shared__ float tile[32][33];
    int bx = blockIdx.x * 32;
    int by = blockIdx.y * 32;
    int tx = threadIdx.x, ty = threadIdx.y;
    #pragma unroll
    for (int j = 0; j < 32; j += 8)
        tile[ty + j][tx] = W[(size_t)(by + ty + j) * N + bx + tx];
    __syncthreads();
    #pragma unroll
    for (int j = 0; j < 32; j += 8) {
        float v = tile[tx][ty + j];
        __nv_bfloat16 h, l;
        split2(v, h, l);
        size_t o = (size_t)(bx + ty + j) * K + by + tx;
        Th[o] = h; Tl[o] = l;
    }
}

// ============================================================
// LayerNorm; optionally also emits bf16 hi/lo splits.
// ============================================================
__global__ __launch_bounds__(256) void ln_kernel(
    const float* __restrict__ X, const float* __restrict__ gam,
    const float* __restrict__ bet, float* __restrict__ Y,
    __nv_bfloat16* __restrict__ Oh, __nv_bfloat16* __restrict__ Ol)
{
    __shared__ float red[256];
    int row = blockIdx.x;
    int t   = threadIdx.x;
    const float* xr = X + (size_t)row * Hv;

    float4 x4 = *(const float4*)&xr[t * 4];
    red[t] = x4.x + x4.y + x4.z + x4.w; __syncthreads();
    #pragma unroll
    for (int s = 128; s > 0; s >>= 1) {
        if (t < s) red[t] += red[t + s];
        __syncthreads();
    }
    float mean = red[0] * (1.0f / Hv);
    __syncthreads();

    float dx = x4.x - mean, dy = x4.y - mean, dz = x4.z - mean, dw = x4.w - mean;
    red[t] = dx * dx + dy * dy + dz * dz + dw * dw; __syncthreads();
    #pragma unroll
    for (int s = 128; s > 0; s >>= 1) {
        if (t < s) red[t] += red[t + s];
        __syncthreads();
    }
    float rstd = rsqrtf(red[0] * (1.0f / Hv) + 1e-12f);

    float4 gg = *(const float4*)&gam[t * 4];
    float4 bb = *(const float4*)&bet[t * 4];
    float4 out;
    out.x = dx * rstd * gg.x + bb.x;
    out.y = dy * rstd * gg.y + bb.y;
    out.z = dz * rstd * gg.z + bb.z;
    out.w = dw * rstd * gg.w + bb.w;
    *(float4*)&Y[(size_t)row * Hv + t * 4] = out;

    if (Oh) {
        size_t o = (size_t)row * Hv + t * 4;
        __nv_bfloat16 h, l;
        split2(out.x, h, l); Oh[o]     = h; Ol[o]     = l;
        split2(out.y, h, l); Oh[o + 1] = h; Ol[o + 1] = l;
        split2(out.z, h, l); Oh[o + 2] = h; Ol[o + 2] = l;
        split2(out.w, h, l); Oh[o + 3] = h; Ol[o + 3] = l;
    }
}

// ============================================================
// Launch
// ============================================================
extern "C" void kernel_launch(void* const* d_in, const int* in_sizes, int n_in,
                              void* d_out, int out_size)
{
    const float* x    = (const float*)d_in[0];
    const float* mask = (const float*)d_in[1];
    const float* Wq   = (const float*)d_in[2];
    const float* bq   = (const float*)d_in[3];
    const float* Wk   = (const float*)d_in[4];
    const float* bk   = (const float*)d_in[5];
    const float* Wv   = (const float*)d_in[6];
    const float* bv   = (const float*)d_in[7];
    const float* Wo   = (const float*)d_in[8];
    const float* bo   = (const float*)d_in[9];
    const float* ln1g = (const float*)d_in[10];
    const float* ln1b = (const float*)d_in[11];
    const float* W1   = (const float*)d_in[12];
    const float* b1   = (const float*)d_in[13];
    const float* W2   = (const float*)d_in[14];
    const float* b2   = (const float*)d_in[15];
    const float* ln2g = (const float*)d_in[16];
    const float* ln2b = (const float*)d_in[17];
    float* out = (float*)d_out;

    float *res1, *x1, *res2;
    __nv_bfloat16 *ah, *al, *fh, *fl;
    __nv_bfloat16 *qh, *ql, *kh, *kl, *vh, *vl;
    __nv_bfloat16 *wqh, *wql, *wkh, *wkl, *wvh, *wvl, *woh, *wol, *w1h, *w1l, *w2h, *w2l;
    cudaGetSymbolAddress((void**)&res1, g_res1);
    cudaGetSymbolAddress((void**)&x1,   g_x1);
    cudaGetSymbolAddress((void**)&res2, g_res2);
    cudaGetSymbolAddress((void**)&ah,   g_ah);
    cudaGetSymbolAddress((void**)&al,   g_al);
    cudaGetSymbolAddress((void**)&fh,   g_fh);
    cudaGetSymbolAddress((void**)&fl,   g_fl);
    cudaGetSymbolAddress((void**)&qh,   g_qh);
    cudaGetSymbolAddress((void**)&ql,   g_ql);
    cudaGetSymbolAddress((void**)&kh,   g_kh);
    cudaGetSymbolAddress((void**)&kl,   g_kl);
    cudaGetSymbolAddress((void**)&vh,   g_vh);
    cudaGetSymbolAddress((void**)&vl,   g_vl);
    cudaGetSymbolAddress((void**)&wqh,  g_wqh);
    cudaGetSymbolAddress((void**)&wql,  g_wql);
    cudaGetSymbolAddress((void**)&wkh,  g_wkh);
    cudaGetSymbolAddress((void**)&wkl,  g_wkl);
    cudaGetSymbolAddress((void**)&wvh,  g_wvh);
    cudaGetSymbolAddress((void**)&wvl,  g_wvl);
    cudaGetSymbolAddress((void**)&woh,  g_woh);
    cudaGetSymbolAddress((void**)&wol,  g_wol);
    cudaGetSymbolAddress((void**)&w1h,  g_w1h);
    cudaGetSymbolAddress((void**)&w1l,  g_w1l);
    cudaGetSymbolAddress((void**)&w2h,  g_w2h);
    cudaGetSymbolAddress((void**)&w2l,  g_w2l);

    cudaFuncSetAttribute(gemm_mma, cudaFuncAttributeMaxDynamicSharedMemorySize, GSMEM);
    cudaFuncSetAttribute(attn_mma, cudaFuncAttributeMaxDynamicSharedMemorySize, ASMEM);

    dim3 tb(32, 8);
    transpose_split<<<dim3(Hv/32,  Hv/32),  tb>>>(Wq, wqh, wql, Hv, Hv);
    transpose_split<<<dim3(Hv/32,  Hv/32),  tb>>>(Wk, wkh, wkl, Hv, Hv);
    transpose_split<<<dim3(Hv/32,  Hv/32),  tb>>>(Wv, wvh, wvl, Hv, Hv);
    transpose_split<<<dim3(Hv/32,  Hv/32),  tb>>>(Wo, woh, wol, Hv, Hv);
    transpose_split<<<dim3(FFv/32, Hv/32),  tb>>>(W1, w1h, w1l, Hv, FFv);
    transpose_split<<<dim3(Hv/32,  FFv/32), tb>>>(W2, w2h, w2l, FFv, Hv);
    split_k<<<(Mv*Hv)/1024, 256>>>(x, ah, al, Mv*Hv);

    dim3 gH(Hv / 128, Mv / 128);
    dim3 gF(FFv / 128, Mv / 128);

    gemm_mma<<<gH, 256, GSMEM>>>(ah, al, wqh, wql, bq, nullptr, nullptr, qh, ql, Hv, Hv, 0);
    gemm_mma<<<gH, 256, GSMEM>>>(ah, al, wkh, wkl, bk, nullptr, nullptr, kh, kl, Hv, Hv, 0);
    gemm_mma<<<gH, 256, GSMEM>>>(ah, al, wvh, wvl, bv, nullptr, nullptr, vh, vl, Hv, Hv, 0);

    dim3 gA(Sv / 128, NHv, Bv);
    attn_mma<<<gA, 256, ASMEM>>>(qh, ql, kh, kl, vh, vl, mask, ah, al);

    gemm_mma<<<gH, 256, GSMEM>>>(ah, al, woh, wol, bo, x, res1, nullptr, nullptr, Hv, Hv, 0);
    ln_kernel<<<Mv, 256>>>(res1, ln1g, ln1b, x1, ah, al);

    gemm_mma<<<gF, 256, GSMEM>>>(ah, al, w1h, w1l, b1, nullptr, nullptr, fh, fl, Hv, FFv, 1);
    gemm_mma<<<gH, 256, GSMEM>>>(fh, fl, w2h, w2l, b2, x1, res2, nullptr, nullptr, FFv, Hv, 0);
    ln_kernel<<<Mv, 256>>>(res2, ln2g, ln2b, out, nullptr, nullptr);
}

// round 6
// speedup vs baseline: 4.1291x; 1.5156x over previous
#include <cuda_runtime.h>
#include <cuda_fp16.h>
#include <math.h>
#include <stdint.h>

// ---- problem dims ----
#define Bv 4
#define Sv 2048
#define Hv 1024
#define NHv 16
#define HDv 64
#define FFv 4096
#define Mv (Bv*Sv)   // 8192 rows

// ---- scratch (device globals; no allocation allowed) ----
__device__ float g_res1[Mv*Hv];
__device__ float g_x1[Mv*Hv];
__device__ float g_res2[Mv*Hv];

__device__ __half g_ah[Mv*Hv];            // split A operand (x -> ctx -> x1)
__device__ __half g_al[Mv*Hv];
__device__ __half g_qh[Mv*Hv], g_ql[Mv*Hv];
__device__ __half g_kq[Mv*Hv];            // K, V single fp16
__device__ __half g_vq[Mv*Hv];
__device__ __half g_fh[Mv*FFv];           // FF intermediate split
__device__ __half g_fl[Mv*FFv];
// transposed single-fp16 weights ([N,K] K-major)
__device__ __half g_wq[Hv*Hv], g_wk[Hv*Hv], g_wv[Hv*Hv], g_wo[Hv*Hv];
__device__ __half g_w1[FFv*Hv];
__device__ __half g_w2[Hv*FFv];

// ============================================================
// helpers
// ============================================================
__device__ __forceinline__ uint32_t s2u(const void* p) {
    uint32_t a;
    asm("{ .reg .u64 t; cvta.to.shared.u64 t, %1; cvt.u32.u64 %0, t; }" : "=r"(a) : "l"(p));
    return a;
}
__device__ __forceinline__ void split2h(float a, __half& h, __half& l) {
    h = __float2half_rn(a);
    l = __float2half_rn(a - __half2float(h));
}
__device__ __forceinline__ void cpasync16(uint32_t dst, const void* src) {
    asm volatile("cp.async.cg.shared.global [%0], [%1], 16;" :: "r"(dst), "l"(src));
}
#define CP_COMMIT() asm volatile("cp.async.commit_group;" ::: "memory")
#define CP_WAIT(n)  asm volatile("cp.async.wait_group %0;" :: "n"(n) : "memory")

__device__ __forceinline__ void ldsm4(uint32_t& r0, uint32_t& r1, uint32_t& r2, uint32_t& r3,
                                      uint32_t addr) {
    asm volatile("ldmatrix.sync.aligned.m8n8.x4.shared.b16 {%0,%1,%2,%3}, [%4];"
                 : "=r"(r0), "=r"(r1), "=r"(r2), "=r"(r3) : "r"(addr));
}
__device__ __forceinline__ void ldsm4t(uint32_t& r0, uint32_t& r1, uint32_t& r2, uint32_t& r3,
                                       uint32_t addr) {
    asm volatile("ldmatrix.sync.aligned.m8n8.x4.trans.shared.b16 {%0,%1,%2,%3}, [%4];"
                 : "=r"(r0), "=r"(r1), "=r"(r2), "=r"(r3) : "r"(addr));
}
__device__ __forceinline__ void mma16816(float* d, const uint32_t* a, const uint32_t* b) {
    asm volatile("mma.sync.aligned.m16n8k16.row.col.f32.f16.f16.f32 "
                 "{%0,%1,%2,%3}, {%4,%5,%6,%7}, {%8,%9}, {%0,%1,%2,%3};"
                 : "+f"(d[0]), "+f"(d[1]), "+f"(d[2]), "+f"(d[3])
                 : "r"(a[0]), "r"(a[1]), "r"(a[2]), "r"(a[3]), "r"(b[0]), "r"(b[1]));
}
__device__ __forceinline__ uint32_t packh2(float lo, float hi) {
    uint32_t r;
    asm("cvt.rn.f16x2.f32 %0, %1, %2;" : "=r"(r) : "f"(hi), "f"(lo));
    return r;
}
#define SWZ(o) ((o) ^ (((o) >> 3) & 0x70))

// ============================================================
// Split-fp16 tensor-core GEMM (2 MMA passes):
//   C = (Ah + Al) @ Bq^T ; A split fp16, B single fp16 [N,K].
// BM=128, BN=128, BK=32; 4-stage cp.async pipeline (3 tiles/stage).
// ============================================================
#define BKc 32
#define TILE_BYTES 8192              // 128 rows * 64B
#define STAGE_BYTES (3*TILE_BYTES)   // Ah, Al, Bq
#define GSMEM (4*STAGE_BYTES)        // 96KB

__global__ __launch_bounds__(256) void gemm_mma(
    const __half* __restrict__ Ah, const __half* __restrict__ Al,
    const __half* __restrict__ Bq,
    const float* __restrict__ bias, const float* __restrict__ resid,
    float* __restrict__ C, __half* __restrict__ Ch, __half* __restrict__ Cl,
    int K, int N, int act)
{
    extern __shared__ __align__(1024) char smem[];
    uint32_t sb = s2u(smem);
    int t = threadIdx.x, lane = t & 31, warp = t >> 5;
    int wm = warp & 1, wn = warp >> 1;
    int bm = blockIdx.y * 128, bn = blockIdx.x * 128;

    const __half* srcs[3];
    srcs[0] = Ah + (size_t)bm * K;
    srcs[1] = Al + (size_t)bm * K;
    srcs[2] = Bq + (size_t)bn * K;

    float acc[4][4][4];
    #pragma unroll
    for (int i = 0; i < 4; i++)
        #pragma unroll
        for (int j = 0; j < 4; j++)
            #pragma unroll
            for (int e = 0; e < 4; e++) acc[i][j][e] = 0.f;

    int nc = K / BKc;

    auto load_stage = [&](int s, int c) {
        int kb = c * BKc;
        #pragma unroll
        for (int i = 0; i < 6; i++) {
            int idx = i * 256 + t;          // 0..1535
            int o   = idx >> 9;             // 0..2
            int rem = idx & 511;
            int r   = rem >> 2;
            int ch  = rem & 3;
            const __half* src = srcs[o] + (size_t)r * K + kb + ch * 8;
            uint32_t dst = sb + s * STAGE_BYTES + o * TILE_BYTES
                         + r * 64 + ((ch ^ ((r >> 1) & 3)) << 4);
            cpasync16(dst, src);
        }
    };

    #pragma unroll
    for (int i = 0; i < 3; i++) { load_stage(i, i); CP_COMMIT(); }

    for (int c = 0; c < nc; c++) {
        CP_WAIT(2);
        __syncthreads();
        if (c + 3 < nc) { load_stage((c + 3) & 3, c + 3); CP_COMMIT(); }

        uint32_t tb = sb + (c & 3) * STAGE_BYTES;
        int g = lane >> 3;

        #pragma unroll
        for (int ks = 0; ks < 2; ks++) {
            uint32_t aH[4][4], aL[4][4], bQ[4][2];
            {
                int arow_off = ((g & 1) << 3) + (lane & 7);
                int ach = 2 * ks + (g >> 1);
                #pragma unroll
                for (int mf = 0; mf < 4; mf++) {
                    int row = wm * 64 + mf * 16 + arow_off;
                    uint32_t ad = tb + row * 64 + ((ach ^ ((row >> 1) & 3)) << 4);
                    ldsm4(aH[mf][0], aH[mf][1], aH[mf][2], aH[mf][3], ad);
                    ldsm4(aL[mf][0], aL[mf][1], aL[mf][2], aL[mf][3], ad + TILE_BYTES);
                }
            }
            {
                int brow_off = ((g >> 1) << 3) + (lane & 7);
                int bch = 2 * ks + (g & 1);
                #pragma unroll
                for (int np = 0; np < 2; np++) {
                    int row = wn * 32 + np * 16 + brow_off;
                    uint32_t bd = tb + 2 * TILE_BYTES + row * 64
                                + ((bch ^ ((row >> 1) & 3)) << 4);
                    ldsm4(bQ[2*np][0], bQ[2*np][1], bQ[2*np+1][0], bQ[2*np+1][1], bd);
                }
            }
            #pragma unroll
            for (int mf = 0; mf < 4; mf++)
                #pragma unroll
                for (int nf = 0; nf < 4; nf++) {
                    mma16816(acc[mf][nf], aH[mf], bQ[nf]);
                    mma16816(acc[mf][nf], aL[mf], bQ[nf]);
                }
        }
    }

    #pragma unroll
    for (int mf = 0; mf < 4; mf++) {
        int r0 = bm + wm * 64 + mf * 16 + (lane >> 2);
        #pragma unroll
        for (int nf = 0; nf < 4; nf++) {
            int j = bn + wn * 32 + nf * 8 + (lane & 3) * 2;
            float b0 = bias[j], b1 = bias[j + 1];
            #pragma unroll
            for (int half_ = 0; half_ < 2; half_++) {
                int row = r0 + half_ * 8;
                float v0 = acc[mf][nf][half_ * 2 + 0] + b0;
                float v1 = acc[mf][nf][half_ * 2 + 1] + b1;
                if (act) {
                    float xg = v0;
                    v0 = 0.5f * xg * (1.0f + tanhf(0.7978845608028654f *
                            (xg + 0.044715f * xg * xg * xg)));
                    xg = v1;
                    v1 = 0.5f * xg * (1.0f + tanhf(0.7978845608028654f *
                            (xg + 0.044715f * xg * xg * xg)));
                }
                size_t o = (size_t)row * N + j;
                if (resid) { v0 += resid[o]; v1 += resid[o + 1]; }
                if (C) { C[o] = v0; C[o + 1] = v1; }
                if (Ch) {
                    if (Cl) {
                        __half h, l;
                        split2h(v0, h, l); Ch[o]     = h; Cl[o]     = l;
                        split2h(v1, h, l); Ch[o + 1] = h; Cl[o + 1] = l;
                    } else {
                        Ch[o]     = __float2half_rn(v0);
                        Ch[o + 1] = __float2half_rn(v1);
                    }
                }
            }
        }
    }
}

// ============================================================
// Tensor-core flash attention, fp16 2-pass, 3-stage KV pipeline.
// Q split (Qh,Ql); K,V single fp16; P split in registers.
// ============================================================
#define AQ_BYTES 16384
#define AKV_TILE 8192
#define AKV_STAGE (2*AKV_TILE)             // K + V
#define ASMEM (2*AQ_BYTES + 3*AKV_STAGE)   // 80KB

__global__ __launch_bounds__(256) void attn_mma(
    const __half* __restrict__ Qh, const __half* __restrict__ Ql,
    const __half* __restrict__ Kq, const __half* __restrict__ Vq,
    const float* __restrict__ mask,
    __half* __restrict__ Oh, __half* __restrict__ Ol)
{
    extern __shared__ __align__(1024) char smem[];
    uint32_t sb = s2u(smem);
    int t = threadIdx.x, lane = t & 31, warp = t >> 5;
    int qb = blockIdx.x * 128;
    int h  = blockIdx.y;
    int b  = blockIdx.z;
    const size_t bh = (size_t)b * Sv * Hv + (size_t)h * HDv;

    // ---- load Q tiles ----
    {
        const __half* qs[2] = { Qh, Ql };
        #pragma unroll
        for (int i = 0; i < 8; i++) {
            int idx = i * 256 + t;
            int tile = idx >> 10;
            int rem  = idx & 1023;
            int r    = rem >> 3;
            int ch   = rem & 7;
            const __half* src = qs[tile] + bh + (size_t)(qb + r) * Hv + ch * 8;
            uint32_t dst = sb + tile * AQ_BYTES + SWZ(r * 128 + ch * 16);
            cpasync16(dst, src);
        }
        CP_COMMIT();
    }

    const __half* kvsrc[2] = { Kq, Vq };
    auto load_kv = [&](int s, int kb) {
        #pragma unroll
        for (int i = 0; i < 4; i++) {
            int idx  = i * 256 + t;          // 0..1023
            int tile = idx >> 9;             // 0..1
            int rem  = idx & 511;
            int r    = rem >> 3;
            int ch   = rem & 7;
            const __half* src = kvsrc[tile] + bh + (size_t)(kb + r) * Hv + ch * 8;
            uint32_t dst = sb + 2 * AQ_BYTES + s * AKV_STAGE + tile * AKV_TILE
                         + SWZ(r * 128 + ch * 16);
            cpasync16(dst, src);
        }
    };

    load_kv(0, 0);  CP_COMMIT();
    load_kv(1, 64); CP_COMMIT();
    CP_WAIT(2);             // Q arrived
    __syncthreads();

    int g = lane >> 3;
    uint32_t qfh[4][4], qfl[4][4];
    {
        int arow = warp * 16 + ((g & 1) << 3) + (lane & 7);
        #pragma unroll
        for (int ks = 0; ks < 4; ks++) {
            int ach = 2 * ks + (g >> 1);
            uint32_t ad = sb + SWZ(arow * 128 + ach * 16);
            ldsm4(qfh[ks][0], qfh[ks][1], qfh[ks][2], qfh[ks][3], ad);
            ldsm4(qfl[ks][0], qfl[ks][1], qfl[ks][2], qfl[ks][3], ad + AQ_BYTES);
        }
    }

    float oacc[8][4];
    #pragma unroll
    for (int j = 0; j < 8; j++)
        #pragma unroll
        for (int e = 0; e < 4; e++) oacc[j][e] = 0.f;
    float mrow[2] = { -INFINITY, -INFINITY };
    float lrow[2] = { 0.f, 0.f };
    const float* maskRow = mask + (size_t)b * Sv;
    int coff = 2 * (lane & 3);

    const int NIT = Sv / 64;
    for (int it = 0; it < NIT; it++) {
        CP_WAIT(1);
        __syncthreads();
        if (it + 2 < NIT) { load_kv((it + 2) % 3, (it + 2) * 64); CP_COMMIT(); }
        uint32_t stg = sb + 2 * AQ_BYTES + (it % 3) * AKV_STAGE;

        // ---- scores = Q K^T (2 passes) ----
        float sacc[8][4];
        #pragma unroll
        for (int j = 0; j < 8; j++)
            #pragma unroll
            for (int e = 0; e < 4; e++) sacc[j][e] = 0.f;

        #pragma unroll
        for (int ks = 0; ks < 4; ks++) {
            uint32_t kbq[8][2];
            int brow = ((g >> 1) << 3) + (lane & 7);
            int bch  = 2 * ks + (g & 1);
            #pragma unroll
            for (int np = 0; np < 4; np++) {
                int row = np * 16 + brow;
                uint32_t ad = stg + SWZ(row * 128 + bch * 16);
                ldsm4(kbq[2*np][0], kbq[2*np][1], kbq[2*np+1][0], kbq[2*np+1][1], ad);
            }
            #pragma unroll
            for (int j = 0; j < 8; j++) {
                mma16816(sacc[j], qfh[ks], kbq[j]);
                mma16816(sacc[j], qfl[ks], kbq[j]);
            }
        }

        int kb = it * 64;
        #pragma unroll
        for (int j = 0; j < 8; j++) {
            float mk0 = maskRow[kb + 8 * j + coff];
            float mk1 = maskRow[kb + 8 * j + coff + 1];
            sacc[j][0] = sacc[j][0] * 0.125f + mk0;
            sacc[j][1] = sacc[j][1] * 0.125f + mk1;
            sacc[j][2] = sacc[j][2] * 0.125f + mk0;
            sacc[j][3] = sacc[j][3] * 0.125f + mk1;
        }

        #pragma unroll
        for (int rh = 0; rh < 2; rh++) {
            float rmax = -INFINITY;
            #pragma unroll
            for (int j = 0; j < 8; j++)
                rmax = fmaxf(rmax, fmaxf(sacc[j][2*rh], sacc[j][2*rh + 1]));
            rmax = fmaxf(rmax, __shfl_xor_sync(0xffffffffu, rmax, 1));
            rmax = fmaxf(rmax, __shfl_xor_sync(0xffffffffu, rmax, 2));
            float mn   = fmaxf(mrow[rh], rmax);
            float corr = __expf(mrow[rh] - mn);
            float rsum = 0.f;
            #pragma unroll
            for (int j = 0; j < 8; j++) {
                float p0 = __expf(sacc[j][2*rh]     - mn);
                float p1 = __expf(sacc[j][2*rh + 1] - mn);
                sacc[j][2*rh] = p0; sacc[j][2*rh + 1] = p1;
                rsum += p0 + p1;
            }
            rsum += __shfl_xor_sync(0xffffffffu, rsum, 1);
            rsum += __shfl_xor_sync(0xffffffffu, rsum, 2);
            lrow[rh] = lrow[rh] * corr + rsum;
            mrow[rh] = mn;
            #pragma unroll
            for (int j = 0; j < 8; j++) {
                oacc[j][2*rh]     *= corr;
                oacc[j][2*rh + 1] *= corr;
            }
        }

        // ---- O += P V (2 passes, P split in registers) ----
        int vkey0  = ((lane >> 3) & 1) * 8 + (lane & 7);
        int vbyte0 = ((lane >> 4) & 1) * 16;
        #pragma unroll
        for (int ks = 0; ks < 4; ks++) {
            uint32_t aPh[4], aPl[4];
            #pragma unroll
            for (int q4 = 0; q4 < 4; q4++) {
                int jj = 2 * ks + (q4 >> 1);
                float p0 = sacc[jj][(q4 & 1) * 2 + 0];
                float p1 = sacc[jj][(q4 & 1) * 2 + 1];
                float h0 = __half2float(__float2half_rn(p0));
                float h1 = __half2float(__float2half_rn(p1));
                aPh[q4] = packh2(h0, h1);
                aPl[q4] = packh2(p0 - h0, p1 - h1);
            }
            uint32_t vbq[8][2];
            int vkey = 16 * ks + vkey0;
            #pragma unroll
            for (int np = 0; np < 4; np++) {
                uint32_t ad = stg + AKV_TILE + SWZ(vkey * 128 + 32 * np + vbyte0);
                ldsm4t(vbq[2*np][0], vbq[2*np][1], vbq[2*np+1][0], vbq[2*np+1][1], ad);
            }
            #pragma unroll
            for (int j = 0; j < 8; j++) {
                mma16816(oacc[j], aPh, vbq[j]);
                mma16816(oacc[j], aPl, vbq[j]);
            }
        }
    }

    #pragma unroll
    for (int rh = 0; rh < 2; rh++) {
        float inv = 1.0f / lrow[rh];
        int row = qb + warp * 16 + (lane >> 2) + 8 * rh;
        #pragma unroll
        for (int j = 0; j < 8; j++) {
            float v0 = oacc[j][2*rh]     * inv;
            float v1 = oacc[j][2*rh + 1] * inv;
            __half h0, l0, h1, l1;
            split2h(v0, h0, l0);
            split2h(v1, h1, l1);
            size_t o = bh + (size_t)row * Hv + 8 * j + coff;
            *(__half2*)&Oh[o] = __half2{h0, h1};
            *(__half2*)&Ol[o] = __half2{l0, l1};
        }
    }
}

// ============================================================
// split: fp32 -> (hi, lo) fp16
// ============================================================
__global__ __launch_bounds__(256) void split_k(
    const float* __restrict__ X, __half* __restrict__ H,
    __half* __restrict__ L, int n)
{
    int i = (blockIdx.x * 256 + threadIdx.x) * 4;
    if (i >= n) return;
    float4 x4 = *(const float4*)&X[i];
    __half h0, l0, h1, l1, h2, l2, h3, l3;
    split2h(x4.x, h0, l0); split2h(x4.y, h1, l1);
    split2h(x4.z, h2, l2); split2h(x4.w, h3, l3);
    H[i] = h0; H[i + 1] = h1; H[i + 2] = h2; H[i + 3] = h3;
    L[i] = l0; L[i + 1] = l1; L[i + 2] = l2; L[i + 3] = l3;
}

// ============================================================
// transpose + quantize: W[K,N] fp32 -> T[N,K] fp16
// ============================================================
__global__ void transpose_quant(const float* __restrict__ W,
                                __half* __restrict__ Th, int K, int N)
{
    __shared__ float tile[32][33];
    int bx = blockIdx.x * 32;
    int by = blockIdx.y * 32;
    int tx = threadIdx.x, ty = threadIdx.y;
    #pragma unroll
    for (int j = 0; j < 32; j += 8)
        tile[ty + j][tx] = W[(size_t)(by + ty + j) * N + bx + tx];
    __syncthreads();
    #pragma unroll
    for (int j = 0; j < 32; j += 8) {
        size_t o = (size_t)(bx + ty + j) * K + by + tx;
        Th[o] = __float2half_rn(tile[tx][ty + j]);
    }
}

// ============================================================
// LayerNorm; optionally also emits fp16 hi/lo splits.
// ============================================================
__global__ __launch_bounds__(256) void ln_kernel(
    const float* __restrict__ X, const float* __restrict__ gam,
    const float* __restrict__ bet, float* __restrict__ Y,
    __half* __restrict__ Oh, __half* __restrict__ Ol)
{
    __shared__ float red[256];
    int row = blockIdx.x;
    int t   = threadIdx.x;
    const float* xr = X + (size_t)row * Hv;

    float4 x4 = *(const float4*)&xr[t * 4];
    red[t] = x4.x + x4.y + x4.z + x4.w; __syncthreads();
    #pragma unroll
    for (int s = 128; s > 0; s >>= 1) {
        if (t < s) red[t] += red[t + s];
        __syncthreads();
    }
    float mean = red[0] * (1.0f / Hv);
    __syncthreads();

    float dx = x4.x - mean, dy = x4.y - mean, dz = x4.z - mean, dw = x4.w - mean;
    red[t] = dx * dx + dy * dy + dz * dz + dw * dw; __syncthreads();
    #pragma unroll
    for (int s = 128; s > 0; s >>= 1) {
        if (t < s) red[t] += red[t + s];
        __syncthreads();
    }
    float rstd = rsqrtf(red[0] * (1.0f / Hv) + 1e-12f);

    float4 gg = *(const float4*)&gam[t * 4];
    float4 bb = *(const float4*)&bet[t * 4];
    float4 out;
    out.x = dx * rstd * gg.x + bb.x;
    out.y = dy * rstd * gg.y + bb.y;
    out.z = dz * rstd * gg.z + bb.z;
    out.w = dw * rstd * gg.w + bb.w;
    *(float4*)&Y[(size_t)row * Hv + t * 4] = out;

    if (Oh) {
        size_t o = (size_t)row * Hv + t * 4;
        __half h, l;
        split2h(out.x, h, l); Oh[o]     = h; Ol[o]     = l;
        split2h(out.y, h, l); Oh[o + 1] = h; Ol[o + 1] = l;
        split2h(out.z, h, l); Oh[o + 2] = h; Ol[o + 2] = l;
        split2h(out.w, h, l); Oh[o + 3] = h; Ol[o + 3] = l;
    }
}

// ============================================================
// Launch
// ============================================================
extern "C" void kernel_launch(void* const* d_in, const int* in_sizes, int n_in,
                              void* d_out, int out_size)
{
    const float* x    = (const float*)d_in[0];
    const float* mask = (const float*)d_in[1];
    const float* Wq   = (const float*)d_in[2];
    const float* bq   = (const float*)d_in[3];
    const float* Wk   = (const float*)d_in[4];
    const float* bk   = (const float*)d_in[5];
    const float* Wv   = (const float*)d_in[6];
    const float* bv   = (const float*)d_in[7];
    const float* Wo   = (const float*)d_in[8];
    const float* bo   = (const float*)d_in[9];
    const float* ln1g = (const float*)d_in[10];
    const float* ln1b = (const float*)d_in[11];
    const float* W1   = (const float*)d_in[12];
    const float* b1   = (const float*)d_in[13];
    const float* W2   = (const float*)d_in[14];
    const float* b2   = (const float*)d_in[15];
    const float* ln2g = (const float*)d_in[16];
    const float* ln2b = (const float*)d_in[17];
    float* out = (float*)d_out;

    float *res1, *x1, *res2;
    __half *ah, *al, *fh, *fl, *qh, *ql, *kq, *vq;
    __half *wq, *wk, *wv, *wo, *w1, *w2;
    cudaGetSymbolAddress((void**)&res1, g_res1);
    cudaGetSymbolAddress((void**)&x1,   g_x1);
    cudaGetSymbolAddress((void**)&res2, g_res2);
    cudaGetSymbolAddress((void**)&ah,   g_ah);
    cudaGetSymbolAddress((void**)&al,   g_al);
    cudaGetSymbolAddress((void**)&fh,   g_fh);
    cudaGetSymbolAddress((void**)&fl,   g_fl);
    cudaGetSymbolAddress((void**)&qh,   g_qh);
    cudaGetSymbolAddress((void**)&ql,   g_ql);
    cudaGetSymbolAddress((void**)&kq,   g_kq);
    cudaGetSymbolAddress((void**)&vq,   g_vq);
    cudaGetSymbolAddress((void**)&wq,   g_wq);
    cudaGetSymbolAddress((void**)&wk,   g_wk);
    cudaGetSymbolAddress((void**)&wv,   g_wv);
    cudaGetSymbolAddress((void**)&wo,   g_wo);
    cudaGetSymbolAddress((void**)&w1,   g_w1);
    cudaGetSymbolAddress((void**)&w2,   g_w2);

    cudaFuncSetAttribute(gemm_mma, cudaFuncAttributeMaxDynamicSharedMemorySize, GSMEM);
    cudaFuncSetAttribute(attn_mma, cudaFuncAttributeMaxDynamicSharedMemorySize, ASMEM);

    dim3 tb(32, 8);
    transpose_quant<<<dim3(Hv/32,  Hv/32),  tb>>>(Wq, wq, Hv, Hv);
    transpose_quant<<<dim3(Hv/32,  Hv/32),  tb>>>(Wk, wk, Hv, Hv);
    transpose_quant<<<dim3(Hv/32,  Hv/32),  tb>>>(Wv, wv, Hv, Hv);
    transpose_quant<<<dim3(Hv/32,  Hv/32),  tb>>>(Wo, wo, Hv, Hv);
    transpose_quant<<<dim3(FFv/32, Hv/32),  tb>>>(W1, w1, Hv, FFv);
    transpose_quant<<<dim3(Hv/32,  FFv/32), tb>>>(W2, w2, FFv, Hv);
    split_k<<<(Mv*Hv)/1024, 256>>>(x, ah, al, Mv*Hv);

    dim3 gH(Hv / 128, Mv / 128);
    dim3 gF(FFv / 128, Mv / 128);

    // QKV: Q split, K/V single fp16
    gemm_mma<<<gH, 256, GSMEM>>>(ah, al, wq, bq, nullptr, nullptr, qh, ql, Hv, Hv, 0);
    gemm_mma<<<gH, 256, GSMEM>>>(ah, al, wk, bk, nullptr, nullptr, kq, nullptr, Hv, Hv, 0);
    gemm_mma<<<gH, 256, GSMEM>>>(ah, al, wv, bv, nullptr, nullptr, vq, nullptr, Hv, Hv, 0);

    dim3 gA(Sv / 128, NHv, Bv);
    attn_mma<<<gA, 256, ASMEM>>>(qh, ql, kq, vq, mask, ah, al);

    gemm_mma<<<gH, 256, GSMEM>>>(ah, al, wo, bo, x, res1, nullptr, nullptr, Hv, Hv, 0);
    ln_kernel<<<Mv, 256>>>(res1, ln1g, ln1b, x1, ah, al);

    gemm_mma<<<gF, 256, GSMEM>>>(ah, al, w1, b1, nullptr, nullptr, fh, fl, Hv, FFv, 1);
    gemm_mma<<<gH, 256, GSMEM>>>(fh, fl, w2, b2, x1, res2, nullptr, nullptr, FFv, Hv, 0);
    ln_kernel<<<Mv, 256>>>(res2, ln2g, ln2b, out, nullptr, nullptr);
}

// round 7
// speedup vs baseline: 7.5887x; 1.8379x over previous
#include <cuda_runtime.h>
#include <cuda_fp16.h>
#include <math.h>
#include <stdint.h>

// ---- problem dims ----
#define Bv 4
#define Sv 2048
#define Hv 1024
#define NHv 16
#define HDv 64
#define FFv 4096
#define Mv (Bv*Sv)   // 8192 rows

// ---- scratch (device globals; no allocation allowed) ----
__device__ float g_res1[Mv*Hv];
__device__ float g_x1[Mv*Hv];
__device__ float g_res2[Mv*Hv];

__device__ __half g_aq[Mv*Hv];            // fp16 activations (x -> ctx -> x1)
__device__ __half g_qq[Mv*Hv];
__device__ __half g_kq[Mv*Hv];
__device__ __half g_vq[Mv*Hv];
__device__ __half g_fq[Mv*FFv];           // FF intermediate
// transposed fp16 weights ([N,K] K-major)
__device__ __half g_wq[Hv*Hv], g_wk[Hv*Hv], g_wv[Hv*Hv], g_wo[Hv*Hv];
__device__ __half g_w1[FFv*Hv];
__device__ __half g_w2[Hv*FFv];

// ============================================================
// helpers
// ============================================================
__device__ __forceinline__ uint32_t s2u(const void* p) {
    uint32_t a;
    asm("{ .reg .u64 t; cvta.to.shared.u64 t, %1; cvt.u32.u64 %0, t; }" : "=r"(a) : "l"(p));
    return a;
}
__device__ __forceinline__ void cpasync16(uint32_t dst, const void* src) {
    asm volatile("cp.async.cg.shared.global [%0], [%1], 16;" :: "r"(dst), "l"(src));
}
#define CP_COMMIT() asm volatile("cp.async.commit_group;" ::: "memory")
#define CP_WAIT(n)  asm volatile("cp.async.wait_group %0;" :: "n"(n) : "memory")

__device__ __forceinline__ void ldsm4(uint32_t& r0, uint32_t& r1, uint32_t& r2, uint32_t& r3,
                                      uint32_t addr) {
    asm volatile("ldmatrix.sync.aligned.m8n8.x4.shared.b16 {%0,%1,%2,%3}, [%4];"
                 : "=r"(r0), "=r"(r1), "=r"(r2), "=r"(r3) : "r"(addr));
}
__device__ __forceinline__ void ldsm4t(uint32_t& r0, uint32_t& r1, uint32_t& r2, uint32_t& r3,
                                       uint32_t addr) {
    asm volatile("ldmatrix.sync.aligned.m8n8.x4.trans.shared.b16 {%0,%1,%2,%3}, [%4];"
                 : "=r"(r0), "=r"(r1), "=r"(r2), "=r"(r3) : "r"(addr));
}
__device__ __forceinline__ void mma16816(float* d, const uint32_t* a, const uint32_t* b) {
    asm volatile("mma.sync.aligned.m16n8k16.row.col.f32.f16.f16.f32 "
                 "{%0,%1,%2,%3}, {%4,%5,%6,%7}, {%8,%9}, {%0,%1,%2,%3};"
                 : "+f"(d[0]), "+f"(d[1]), "+f"(d[2]), "+f"(d[3])
                 : "r"(a[0]), "r"(a[1]), "r"(a[2]), "r"(a[3]), "r"(b[0]), "r"(b[1]));
}
__device__ __forceinline__ uint32_t packh2(float lo, float hi) {
    uint32_t r;
    asm("cvt.rn.f16x2.f32 %0, %1, %2;" : "=r"(r) : "f"(hi), "f"(lo));
    return r;
}
#define SWZ(o) ((o) ^ (((o) >> 3) & 0x70))

// ============================================================
// fp16 tensor-core GEMM (single MMA pass):
//   C = Aq @ Bq^T ; both single fp16, B is [N,K] K-major.
// BM=128, BN=128, BK=32; 4-stage cp.async pipeline (2 tiles/stage).
// ============================================================
#define BKc 32
#define TILE_BYTES 8192              // 128 rows * 64B
#define STAGE_BYTES (2*TILE_BYTES)   // Aq, Bq
#define GSMEM (4*STAGE_BYTES)        // 64KB

__global__ __launch_bounds__(256) void gemm_mma(
    const __half* __restrict__ Aq, const __half* __restrict__ Bq,
    const float* __restrict__ bias, const float* __restrict__ resid,
    float* __restrict__ C, __half* __restrict__ Cq,
    int K, int N, int act)
{
    extern __shared__ __align__(1024) char smem[];
    uint32_t sb = s2u(smem);
    int t = threadIdx.x, lane = t & 31, warp = t >> 5;
    int wm = warp & 1, wn = warp >> 1;
    int bm = blockIdx.y * 128, bn = blockIdx.x * 128;

    const __half* srcs[2];
    srcs[0] = Aq + (size_t)bm * K;
    srcs[1] = Bq + (size_t)bn * K;

    float acc[4][4][4];
    #pragma unroll
    for (int i = 0; i < 4; i++)
        #pragma unroll
        for (int j = 0; j < 4; j++)
            #pragma unroll
            for (int e = 0; e < 4; e++) acc[i][j][e] = 0.f;

    int nc = K / BKc;

    auto load_stage = [&](int s, int c) {
        int kb = c * BKc;
        #pragma unroll
        for (int i = 0; i < 4; i++) {
            int idx = i * 256 + t;          // 0..1023
            int o   = idx >> 9;             // 0..1
            int rem = idx & 511;
            int r   = rem >> 2;
            int ch  = rem & 3;
            const __half* src = srcs[o] + (size_t)r * K + kb + ch * 8;
            uint32_t dst = sb + s * STAGE_BYTES + o * TILE_BYTES
                         + r * 64 + ((ch ^ ((r >> 1) & 3)) << 4);
            cpasync16(dst, src);
        }
    };

    #pragma unroll
    for (int i = 0; i < 3; i++) { load_stage(i, i); CP_COMMIT(); }

    for (int c = 0; c < nc; c++) {
        CP_WAIT(2);
        __syncthreads();
        if (c + 3 < nc) { load_stage((c + 3) & 3, c + 3); CP_COMMIT(); }

        uint32_t tb = sb + (c & 3) * STAGE_BYTES;
        int g = lane >> 3;

        #pragma unroll
        for (int ks = 0; ks < 2; ks++) {
            uint32_t aQ[4][4], bQ[4][2];
            {
                int arow_off = ((g & 1) << 3) + (lane & 7);
                int ach = 2 * ks + (g >> 1);
                #pragma unroll
                for (int mf = 0; mf < 4; mf++) {
                    int row = wm * 64 + mf * 16 + arow_off;
                    uint32_t ad = tb + row * 64 + ((ach ^ ((row >> 1) & 3)) << 4);
                    ldsm4(aQ[mf][0], aQ[mf][1], aQ[mf][2], aQ[mf][3], ad);
                }
            }
            {
                int brow_off = ((g >> 1) << 3) + (lane & 7);
                int bch = 2 * ks + (g & 1);
                #pragma unroll
                for (int np = 0; np < 2; np++) {
                    int row = wn * 32 + np * 16 + brow_off;
                    uint32_t bd = tb + TILE_BYTES + row * 64
                                + ((bch ^ ((row >> 1) & 3)) << 4);
                    ldsm4(bQ[2*np][0], bQ[2*np][1], bQ[2*np+1][0], bQ[2*np+1][1], bd);
                }
            }
            #pragma unroll
            for (int mf = 0; mf < 4; mf++)
                #pragma unroll
                for (int nf = 0; nf < 4; nf++)
                    mma16816(acc[mf][nf], aQ[mf], bQ[nf]);
        }
    }

    #pragma unroll
    for (int mf = 0; mf < 4; mf++) {
        int r0 = bm + wm * 64 + mf * 16 + (lane >> 2);
        #pragma unroll
        for (int nf = 0; nf < 4; nf++) {
            int j = bn + wn * 32 + nf * 8 + (lane & 3) * 2;
            float b0 = bias[j], b1 = bias[j + 1];
            #pragma unroll
            for (int half_ = 0; half_ < 2; half_++) {
                int row = r0 + half_ * 8;
                float v0 = acc[mf][nf][half_ * 2 + 0] + b0;
                float v1 = acc[mf][nf][half_ * 2 + 1] + b1;
                if (act) {
                    float xg = v0;
                    v0 = 0.5f * xg * (1.0f + tanhf(0.7978845608028654f *
                            (xg + 0.044715f * xg * xg * xg)));
                    xg = v1;
                    v1 = 0.5f * xg * (1.0f + tanhf(0.7978845608028654f *
                            (xg + 0.044715f * xg * xg * xg)));
                }
                size_t o = (size_t)row * N + j;
                if (resid) { v0 += resid[o]; v1 += resid[o + 1]; }
                if (C) { C[o] = v0; C[o + 1] = v1; }
                if (Cq) *(__half2*)&Cq[o] = __half2{__float2half_rn(v0),
                                                    __float2half_rn(v1)};
            }
        }
    }
}

// ============================================================
// Tensor-core flash attention, single-pass fp16, 3-stage KV pipeline.
// ============================================================
#define AQ_BYTES 16384
#define AKV_TILE 8192
#define AKV_STAGE (2*AKV_TILE)             // K + V
#define ASMEM (AQ_BYTES + 3*AKV_STAGE)     // 64KB

__global__ __launch_bounds__(256) void attn_mma(
    const __half* __restrict__ Qq, const __half* __restrict__ Kq,
    const __half* __restrict__ Vq, const float* __restrict__ mask,
    __half* __restrict__ Oq)
{
    extern __shared__ __align__(1024) char smem[];
    uint32_t sb = s2u(smem);
    int t = threadIdx.x, lane = t & 31, warp = t >> 5;
    int qb = blockIdx.x * 128;
    int h  = blockIdx.y;
    int b  = blockIdx.z;
    const size_t bh = (size_t)b * Sv * Hv + (size_t)h * HDv;

    // ---- load Q tile ----
    #pragma unroll
    for (int i = 0; i < 4; i++) {
        int idx = i * 256 + t;             // 0..1023
        int r   = idx >> 3;
        int ch  = idx & 7;
        const __half* src = Qq + bh + (size_t)(qb + r) * Hv + ch * 8;
        cpasync16(sb + SWZ(r * 128 + ch * 16), src);
    }
    CP_COMMIT();

    const __half* kvsrc[2] = { Kq, Vq };
    auto load_kv = [&](int s, int kb) {
        #pragma unroll
        for (int i = 0; i < 4; i++) {
            int idx  = i * 256 + t;
            int tile = idx >> 9;
            int rem  = idx & 511;
            int r    = rem >> 3;
            int ch   = rem & 7;
            const __half* src = kvsrc[tile] + bh + (size_t)(kb + r) * Hv + ch * 8;
            uint32_t dst = sb + AQ_BYTES + s * AKV_STAGE + tile * AKV_TILE
                         + SWZ(r * 128 + ch * 16);
            cpasync16(dst, src);
        }
    };

    load_kv(0, 0);  CP_COMMIT();
    load_kv(1, 64); CP_COMMIT();
    CP_WAIT(2);             // Q arrived
    __syncthreads();

    int g = lane >> 3;
    uint32_t qf[4][4];
    {
        int arow = warp * 16 + ((g & 1) << 3) + (lane & 7);
        #pragma unroll
        for (int ks = 0; ks < 4; ks++) {
            int ach = 2 * ks + (g >> 1);
            uint32_t ad = sb + SWZ(arow * 128 + ach * 16);
            ldsm4(qf[ks][0], qf[ks][1], qf[ks][2], qf[ks][3], ad);
        }
    }

    float oacc[8][4];
    #pragma unroll
    for (int j = 0; j < 8; j++)
        #pragma unroll
        for (int e = 0; e < 4; e++) oacc[j][e] = 0.f;
    float mrow[2] = { -INFINITY, -INFINITY };
    float lrow[2] = { 0.f, 0.f };
    const float* maskRow = mask + (size_t)b * Sv;
    int coff = 2 * (lane & 3);

    const int NIT = Sv / 64;
    for (int it = 0; it < NIT; it++) {
        CP_WAIT(1);
        __syncthreads();
        if (it + 2 < NIT) { load_kv((it + 2) % 3, (it + 2) * 64); CP_COMMIT(); }
        uint32_t stg = sb + AQ_BYTES + (it % 3) * AKV_STAGE;

        // ---- scores = Q K^T ----
        float sacc[8][4];
        #pragma unroll
        for (int j = 0; j < 8; j++)
            #pragma unroll
            for (int e = 0; e < 4; e++) sacc[j][e] = 0.f;

        #pragma unroll
        for (int ks = 0; ks < 4; ks++) {
            uint32_t kbq[8][2];
            int brow = ((g >> 1) << 3) + (lane & 7);
            int bch  = 2 * ks + (g & 1);
            #pragma unroll
            for (int np = 0; np < 4; np++) {
                int row = np * 16 + brow;
                uint32_t ad = stg + SWZ(row * 128 + bch * 16);
                ldsm4(kbq[2*np][0], kbq[2*np][1], kbq[2*np+1][0], kbq[2*np+1][1], ad);
            }
            #pragma unroll
            for (int j = 0; j < 8; j++)
                mma16816(sacc[j], qf[ks], kbq[j]);
        }

        int kb = it * 64;
        #pragma unroll
        for (int j = 0; j < 8; j++) {
            float mk0 = maskRow[kb + 8 * j + coff];
            float mk1 = maskRow[kb + 8 * j + coff + 1];
            sacc[j][0] = sacc[j][0] * 0.125f + mk0;
            sacc[j][1] = sacc[j][1] * 0.125f + mk1;
            sacc[j][2] = sacc[j][2] * 0.125f + mk0;
            sacc[j][3] = sacc[j][3] * 0.125f + mk1;
        }

        #pragma unroll
        for (int rh = 0; rh < 2; rh++) {
            float rmax = -INFINITY;
            #pragma unroll
            for (int j = 0; j < 8; j++)
                rmax = fmaxf(rmax, fmaxf(sacc[j][2*rh], sacc[j][2*rh + 1]));
            rmax = fmaxf(rmax, __shfl_xor_sync(0xffffffffu, rmax, 1));
            rmax = fmaxf(rmax, __shfl_xor_sync(0xffffffffu, rmax, 2));
            float mn   = fmaxf(mrow[rh], rmax);
            float corr = __expf(mrow[rh] - mn);
            float rsum = 0.f;
            #pragma unroll
            for (int j = 0; j < 8; j++) {
                float p0 = __expf(sacc[j][2*rh]     - mn);
                float p1 = __expf(sacc[j][2*rh + 1] - mn);
                sacc[j][2*rh] = p0; sacc[j][2*rh + 1] = p1;
                rsum += p0 + p1;
            }
            rsum += __shfl_xor_sync(0xffffffffu, rsum, 1);
            rsum += __shfl_xor_sync(0xffffffffu, rsum, 2);
            lrow[rh] = lrow[rh] * corr + rsum;
            mrow[rh] = mn;
            #pragma unroll
            for (int j = 0; j < 8; j++) {
                oacc[j][2*rh]     *= corr;
                oacc[j][2*rh + 1] *= corr;
            }
        }

        // ---- O += P V (P quantized fp16 in registers) ----
        int vkey0  = ((lane >> 3) & 1) * 8 + (lane & 7);
        int vbyte0 = ((lane >> 4) & 1) * 16;
        #pragma unroll
        for (int ks = 0; ks < 4; ks++) {
            uint32_t aP[4];
            #pragma unroll
            for (int q4 = 0; q4 < 4; q4++) {
                int jj = 2 * ks + (q4 >> 1);
                aP[q4] = packh2(sacc[jj][(q4 & 1) * 2 + 0],
                                sacc[jj][(q4 & 1) * 2 + 1]);
            }
            uint32_t vbq[8][2];
            int vkey = 16 * ks + vkey0;
            #pragma unroll
            for (int np = 0; np < 4; np++) {
                uint32_t ad = stg + AKV_TILE + SWZ(vkey * 128 + 32 * np + vbyte0);
                ldsm4t(vbq[2*np][0], vbq[2*np][1], vbq[2*np+1][0], vbq[2*np+1][1], ad);
            }
            #pragma unroll
            for (int j = 0; j < 8; j++)
                mma16816(oacc[j], aP, vbq[j]);
        }
    }

    #pragma unroll
    for (int rh = 0; rh < 2; rh++) {
        float inv = 1.0f / lrow[rh];
        int row = qb + warp * 16 + (lane >> 2) + 8 * rh;
        #pragma unroll
        for (int j = 0; j < 8; j++) {
            float v0 = oacc[j][2*rh]     * inv;
            float v1 = oacc[j][2*rh + 1] * inv;
            size_t o = bh + (size_t)row * Hv + 8 * j + coff;
            *(__half2*)&Oq[o] = __half2{__float2half_rn(v0), __float2half_rn(v1)};
        }
    }
}

// ============================================================
// quantize: fp32 -> fp16
// ============================================================
__global__ __launch_bounds__(256) void quant_k(
    const float* __restrict__ X, __half* __restrict__ Q, int n)
{
    int i = (blockIdx.x * 256 + threadIdx.x) * 4;
    if (i >= n) return;
    float4 x4 = *(const float4*)&X[i];
    __half2 a{__float2half_rn(x4.x), __float2half_rn(x4.y)};
    __half2 b{__float2half_rn(x4.z), __float2half_rn(x4.w)};
    *(__half2*)&Q[i]     = a;
    *(__half2*)&Q[i + 2] = b;
}

// ============================================================
// transpose + quantize: W[K,N] fp32 -> T[N,K] fp16
// ============================================================
__global__ void transpose_quant(const float* __restrict__ W,
                                __half* __restrict__ Th, int K, int N)
{
    __shared__ float tile[32][33];
    int bx = blockIdx.x * 32;
    int by = blockIdx.y * 32;
    int tx = threadIdx.x, ty = threadIdx.y;
    #pragma unroll
    for (int j = 0; j < 32; j += 8)
        tile[ty + j][tx] = W[(size_t)(by + ty + j) * N + bx + tx];
    __syncthreads();
    #pragma unroll
    for (int j = 0; j < 32; j += 8) {
        size_t o = (size_t)(bx + ty + j) * K + by + tx;
        Th[o] = __float2half_rn(tile[tx][ty + j]);
    }
}

// ============================================================
// LayerNorm; optionally also emits fp16.
// ============================================================
__global__ __launch_bounds__(256) void ln_kernel(
    const float* __restrict__ X, const float* __restrict__ gam,
    const float* __restrict__ bet, float* __restrict__ Y,
    __half* __restrict__ Oq)
{
    __shared__ float red[256];
    int row = blockIdx.x;
    int t   = threadIdx.x;
    const float* xr = X + (size_t)row * Hv;

    float4 x4 = *(const float4*)&xr[t * 4];
    red[t] = x4.x + x4.y + x4.z + x4.w; __syncthreads();
    #pragma unroll
    for (int s = 128; s > 0; s >>= 1) {
        if (t < s) red[t] += red[t + s];
        __syncthreads();
    }
    float mean = red[0] * (1.0f / Hv);
    __syncthreads();

    float dx = x4.x - mean, dy = x4.y - mean, dz = x4.z - mean, dw = x4.w - mean;
    red[t] = dx * dx + dy * dy + dz * dz + dw * dw; __syncthreads();
    #pragma unroll
    for (int s = 128; s > 0; s >>= 1) {
        if (t < s) red[t] += red[t + s];
        __syncthreads();
    }
    float rstd = rsqrtf(red[0] * (1.0f / Hv) + 1e-12f);

    float4 gg = *(const float4*)&gam[t * 4];
    float4 bb = *(const float4*)&bet[t * 4];
    float4 out;
    out.x = dx * rstd * gg.x + bb.x;
    out.y = dy * rstd * gg.y + bb.y;
    out.z = dz * rstd * gg.z + bb.z;
    out.w = dw * rstd * gg.w + bb.w;
    *(float4*)&Y[(size_t)row * Hv + t * 4] = out;

    if (Oq) {
        size_t o = (size_t)row * Hv + t * 4;
        *(__half2*)&Oq[o]     = __half2{__float2half_rn(out.x), __float2half_rn(out.y)};
        *(__half2*)&Oq[o + 2] = __half2{__float2half_rn(out.z), __float2half_rn(out.w)};
    }
}

// ============================================================
// Launch
// ============================================================
extern "C" void kernel_launch(void* const* d_in, const int* in_sizes, int n_in,
                              void* d_out, int out_size)
{
    const float* x    = (const float*)d_in[0];
    const float* mask = (const float*)d_in[1];
    const float* Wq   = (const float*)d_in[2];
    const float* bq   = (const float*)d_in[3];
    const float* Wk   = (const float*)d_in[4];
    const float* bk   = (const float*)d_in[5];
    const float* Wv   = (const float*)d_in[6];
    const float* bv   = (const float*)d_in[7];
    const float* Wo   = (const float*)d_in[8];
    const float* bo   = (const float*)d_in[9];
    const float* ln1g = (const float*)d_in[10];
    const float* ln1b = (const float*)d_in[11];
    const float* W1   = (const float*)d_in[12];
    const float* b1   = (const float*)d_in[13];
    const float* W2   = (const float*)d_in[14];
    const float* b2   = (const float*)d_in[15];
    const float* ln2g = (const float*)d_in[16];
    const float* ln2b = (const float*)d_in[17];
    float* out = (float*)d_out;

    float *res1, *x1, *res2;
    __half *aq, *fq, *qq, *kq, *vq;
    __half *wq, *wk, *wv, *wo, *w1, *w2;
    cudaGetSymbolAddress((void**)&res1, g_res1);
    cudaGetSymbolAddress((void**)&x1,   g_x1);
    cudaGetSymbolAddress((void**)&res2, g_res2);
    cudaGetSymbolAddress((void**)&aq,   g_aq);
    cudaGetSymbolAddress((void**)&fq,   g_fq);
    cudaGetSymbolAddress((void**)&qq,   g_qq);
    cudaGetSymbolAddress((void**)&kq,   g_kq);
    cudaGetSymbolAddress((void**)&vq,   g_vq);
    cudaGetSymbolAddress((void**)&wq,   g_wq);
    cudaGetSymbolAddress((void**)&wk,   g_wk);
    cudaGetSymbolAddress((void**)&wv,   g_wv);
    cudaGetSymbolAddress((void**)&wo,   g_wo);
    cudaGetSymbolAddress((void**)&w1,   g_w1);
    cudaGetSymbolAddress((void**)&w2,   g_w2);

    cudaFuncSetAttribute(gemm_mma, cudaFuncAttributeMaxDynamicSharedMemorySize, GSMEM);
    cudaFuncSetAttribute(attn_mma, cudaFuncAttributeMaxDynamicSharedMemorySize, ASMEM);

    dim3 tb(32, 8);
    transpose_quant<<<dim3(Hv/32,  Hv/32),  tb>>>(Wq, wq, Hv, Hv);
    transpose_quant<<<dim3(Hv/32,  Hv/32),  tb>>>(Wk, wk, Hv, Hv);
    transpose_quant<<<dim3(Hv/32,  Hv/32),  tb>>>(Wv, wv, Hv, Hv);
    transpose_quant<<<dim3(Hv/32,  Hv/32),  tb>>>(Wo, wo, Hv, Hv);
    transpose_quant<<<dim3(FFv/32, Hv/32),  tb>>>(W1, w1, Hv, FFv);
    transpose_quant<<<dim3(Hv/32,  FFv/32), tb>>>(W2, w2, FFv, Hv);
    quant_k<<<(Mv*Hv)/1024, 256>>>(x, aq, Mv*Hv);

    dim3 gH(Hv / 128, Mv / 128);
    dim3 gF(FFv / 128, Mv / 128);

    gemm_mma<<<gH, 256, GSMEM>>>(aq, wq, bq, nullptr, nullptr, qq, Hv, Hv, 0);
    gemm_mma<<<gH, 256, GSMEM>>>(aq, wk, bk, nullptr, nullptr, kq, Hv, Hv, 0);
    gemm_mma<<<gH, 256, GSMEM>>>(aq, wv, bv, nullptr, nullptr, vq, Hv, Hv, 0);

    dim3 gA(Sv / 128, NHv, Bv);
    attn_mma<<<gA, 256, ASMEM>>>(qq, kq, vq, mask, aq);

    gemm_mma<<<gH, 256, GSMEM>>>(aq, wo, bo, x, res1, nullptr, Hv, Hv, 0);
    ln_kernel<<<Mv, 256>>>(res1, ln1g, ln1b, x1, aq);

    gemm_mma<<<gF, 256, GSMEM>>>(aq, w1, b1, nullptr, nullptr, fq, Hv, FFv, 1);
    gemm_mma<<<gH, 256, GSMEM>>>(fq, w2, b2, x1, res2, nullptr, FFv, Hv, 0);
    ln_kernel<<<Mv, 256>>>(res2, ln2g, ln2b, out, nullptr);
}